// round 14
// baseline (speedup 1.0000x reference)
#include <cuda_runtime.h>
#include <cuda_bf16.h>
#include <math.h>
#include <stdint.h>

// Problem constants
#define Lnum 2
#define Bn   2
#define Sn   2048
#define Hn   1024
#define NHn  16
#define DHn  64
#define FFn  4096
#define Mrows (Bn*Sn)   // 4096
#define QKVW 3072

#define LOG2E 1.4426950408889634f

// ---------------- scratch (device globals; no allocation allowed) ----------
__device__ float g_y  [Mrows*Hn];
__device__ float g_x1 [Mrows*Hn];
__device__ float g_x2 [Mrows*Hn];
__device__ float g_bqkv[Lnum*QKVW];

__device__ __nv_bfloat16 g_xh[Mrows*Hn],  g_xl[Mrows*Hn];
__device__ __nv_bfloat16 g_qkvh[(size_t)Mrows*QKVW], g_qkvl[(size_t)Mrows*QKVW];
__device__ __nv_bfloat16 g_cxh[Mrows*Hn], g_cxl[Mrows*Hn];
__device__ __nv_bfloat16 g_fh[(size_t)Mrows*FFn], g_fl[(size_t)Mrows*FFn];

// K-major split weights per layer: [QKV fused 1024x3072 | AO 1024x1024 | WI 1024x4096 | WO 4096x1024]
#define LW_QKV 0
#define LW_AO  3145728
#define LW_I   4194304
#define LW_O   8388608
#define LW_ELEMS 12582912
__device__ __nv_bfloat16 g_wth[(size_t)Lnum*LW_ELEMS];
__device__ __nv_bfloat16 g_wtl[(size_t)Lnum*LW_ELEMS];

// ---------------- PTX helpers (sm_80-era ISA only) ---------------------------
__device__ __forceinline__ uint32_t smem_u32(const void* p) {
    uint32_t a;
    asm("{ .reg .u64 t; cvta.to.shared.u64 t, %1; cvt.u32.u64 %0, t; }" : "=r"(a) : "l"(p));
    return a;
}
__device__ __forceinline__ void ldmx4(uint32_t* r, uint32_t addr) {
    asm volatile("ldmatrix.sync.aligned.m8n8.x4.shared.b16 {%0,%1,%2,%3}, [%4];"
                 : "=r"(r[0]), "=r"(r[1]), "=r"(r[2]), "=r"(r[3]) : "r"(addr));
}
__device__ __forceinline__ void ldmx4t(uint32_t* r, uint32_t addr) {
    asm volatile("ldmatrix.sync.aligned.m8n8.x4.trans.shared.b16 {%0,%1,%2,%3}, [%4];"
                 : "=r"(r[0]), "=r"(r[1]), "=r"(r[2]), "=r"(r[3]) : "r"(addr));
}
__device__ __forceinline__ void mma_bf16(float* c, const uint32_t* a, const uint32_t* b) {
    asm volatile(
        "mma.sync.aligned.m16n8k16.row.col.f32.bf16.bf16.f32 "
        "{%0,%1,%2,%3}, {%4,%5,%6,%7}, {%8,%9}, {%0,%1,%2,%3};"
        : "+f"(c[0]), "+f"(c[1]), "+f"(c[2]), "+f"(c[3])
        : "r"(a[0]), "r"(a[1]), "r"(a[2]), "r"(a[3]), "r"(b[0]), "r"(b[1]));
}
#define CP_COMMIT() asm volatile("cp.async.commit_group;" ::: "memory")
#define CP_WAIT(N)  asm volatile("cp.async.wait_group %0;" :: "n"(N) : "memory")
#define CP16(so, g) asm volatile("cp.async.ca.shared.global [%0], [%1], 16;" :: "r"(so), "l"(g))

// ---------------- conversion kernels ----------------------------------------
__global__ __launch_bounds__(256)
void split_kernel(const float* __restrict__ x, __nv_bfloat16* __restrict__ h,
                  __nv_bfloat16* __restrict__ l, int n4) {
    int i = blockIdx.x * 256 + threadIdx.x;
    if (i >= n4) return;
    float4 v = ((const float4*)x)[i];
    __nv_bfloat16 h0 = __float2bfloat16(v.x);
    __nv_bfloat16 h1 = __float2bfloat16(v.y);
    __nv_bfloat16 h2 = __float2bfloat16(v.z);
    __nv_bfloat16 h3 = __float2bfloat16(v.w);
    ((__nv_bfloat162*)h)[2*i]   = __nv_bfloat162(h0, h1);
    ((__nv_bfloat162*)h)[2*i+1] = __nv_bfloat162(h2, h3);
    ((__nv_bfloat162*)l)[2*i]   = __nv_bfloat162(__float2bfloat16(v.x - __bfloat162float(h0)),
                                                 __float2bfloat16(v.y - __bfloat162float(h1)));
    ((__nv_bfloat162*)l)[2*i+1] = __nv_bfloat162(__float2bfloat16(v.z - __bfloat162float(h2)),
                                                 __float2bfloat16(v.w - __bfloat162float(h3)));
}

// bias concat for BOTH layers
__global__ __launch_bounds__(256)
void bconcat_kernel(const float* __restrict__ bq, const float* __restrict__ bk,
                    const float* __restrict__ bv, float* __restrict__ out) {
    int i = blockIdx.x * 256 + threadIdx.x;
    if (i >= Lnum * QKVW) return;
    int l = i / QKVW, j = i - l * QKVW;
    float v = (j < Hn) ? bq[l * Hn + j]
             : ((j < 2 * Hn) ? bk[l * Hn + j - Hn] : bv[l * Hn + j - 2 * Hn]);
    out[i] = v;
}

// Fused weight split: ALL 12 weight matrices in one launch.
#define NSEG 12
struct WSegTable {
    const float* src[NSEG];
    int N[NSEG], LD[NSEG], OFF[NSEG];
    long long dst[NSEG];
    int cum[NSEG + 1];
};

__global__ __launch_bounds__(256)
void wsplit_all_kernel(WSegTable T, __nv_bfloat16* __restrict__ th,
                       __nv_bfloat16* __restrict__ tl) {
    const int total = T.cum[NSEG];
    for (int i = blockIdx.x * 256 + threadIdx.x; i < total; i += gridDim.x * 256) {
        int s = 0;
#pragma unroll
        for (int j = 1; j < NSEG; j++) s += (i >= T.cum[j]);
        const int i4 = i - T.cum[s];
        const int idx = i4 * 4;
        const int N = T.N[s];
        const int k = idx / N, n = idx - k * N;
        float4 v = *(const float4*)(T.src[s] + idx);
        const size_t o = (size_t)T.dst[s] + (size_t)k * T.LD[s] + T.OFF[s] + n;
        __nv_bfloat16 h0 = __float2bfloat16(v.x);
        __nv_bfloat16 h1 = __float2bfloat16(v.y);
        __nv_bfloat16 h2 = __float2bfloat16(v.z);
        __nv_bfloat16 h3 = __float2bfloat16(v.w);
        *(__nv_bfloat162*)(th + o)     = __nv_bfloat162(h0, h1);
        *(__nv_bfloat162*)(th + o + 2) = __nv_bfloat162(h2, h3);
        *(__nv_bfloat162*)(tl + o) =
            __nv_bfloat162(__float2bfloat16(v.x - __bfloat162float(h0)),
                           __float2bfloat16(v.y - __bfloat162float(h1)));
        *(__nv_bfloat162*)(tl + o + 2) =
            __nv_bfloat162(__float2bfloat16(v.z - __bfloat162float(h2)),
                           __float2bfloat16(v.w - __bfloat162float(h3)));
    }
}

// ---------------- bf16-split GEMM via mma.sync (HMMA) -----------------------
// 128x128 CTA tile, 256 threads (8 warps = 2M x 4N, warp tile 64x32),
// BK=32, 3-stage cp.async pipeline (single barrier/iter), 2 CTAs/SM.
// A [M,K] row-major hi/lo; B [K,N] K-major hi/lo (ldmatrix.trans fragments).
// MODE bits: 1=gelu, 2=resid, 4=split-out (bf16 hi/lo)
#define BKc 32
#define ROWB 80
#define ROWB_B 272
#define MATB_A (128*ROWB)            // 10240
#define MATB_B (32*ROWB_B)           // 8704
#define STAGEB (2*MATB_A + 2*MATB_B) // 37888
#define GSMEM (3*STAGEB)             // 113664

__device__ __forceinline__ float gelu_exact(float x) {
    return 0.5f * x * (1.0f + erff(x * 0.7071067811865475f));
}

// A tile 128x32 bf16 = 512 16B chunks; 2 iters
__device__ __forceinline__ void cp_tile_a(uint32_t sdst, const __nv_bfloat16* __restrict__ src,
                                          int row0, int K, int k0, int tid) {
#pragma unroll
    for (int j = 0; j < 2; j++) {
        int e = tid + j * 256;
        int r = e >> 2, c = e & 3;
        uint32_t so = sdst + (uint32_t)(r * ROWB + c * 16);
        const void* g = src + (size_t)(row0 + r) * K + k0 + c * 8;
        CP16(so, g);
    }
}
// B tile 32x128 bf16 (K-major rows of 256B) = 512 16B chunks; 2 iters
__device__ __forceinline__ void cp_tile_b(uint32_t sdst, const __nv_bfloat16* __restrict__ src,
                                          int n0, int N, int k0, int tid) {
#pragma unroll
    for (int j = 0; j < 2; j++) {
        int e = tid + j * 256;
        int r = e >> 4, c = e & 15;
        uint32_t so = sdst + (uint32_t)(r * ROWB_B + c * 16);
        const void* g = src + (size_t)(k0 + r) * N + n0 + c * 8;
        CP16(so, g);
    }
}

template <int MODE>
__global__ __launch_bounds__(256, 2)
void bgemm_kernel(const __nv_bfloat16* __restrict__ Ah, const __nv_bfloat16* __restrict__ Al,
                  const __nv_bfloat16* __restrict__ Bh, const __nv_bfloat16* __restrict__ Bl,
                  const float* __restrict__ bias, const float* __restrict__ resid,
                  float* __restrict__ C, __nv_bfloat16* __restrict__ Ch,
                  __nv_bfloat16* __restrict__ Cl, int K, int N) {
    extern __shared__ char smem_raw[];
    const uint32_t sb = smem_u32(smem_raw);

    const int tid = threadIdx.x;
    const int lane = tid & 31, wid = tid >> 5;
    const int wm = wid >> 2, wn = wid & 3;    // 2M x 4N warps; warp tile 64x32
    const int bx = blockIdx.x, by = blockIdx.y;
    const int arow0 = by * 128, bcol0 = bx * 128;

    float acc[4][4][4];
#pragma unroll
    for (int i = 0; i < 4; i++)
#pragma unroll
        for (int n = 0; n < 4; n++)
#pragma unroll
            for (int t = 0; t < 4; t++) acc[i][n][t] = 0.f;

    const uint32_t a_off = (uint32_t)((wm * 64 + (lane & 15)) * ROWB + ((lane & 16) ? 16 : 0));
    const uint32_t b_off = (uint32_t)((lane & 15) * ROWB_B + wn * 64 + ((lane & 16) ? 16 : 0));

    const int nk = K / BKc;

    // prologue: chunks 0,1 -> stages 0,1
#pragma unroll
    for (int p = 0; p < 2; ++p) {
        uint32_t st = sb + (uint32_t)(p * STAGEB);
        cp_tile_a(st,                       Ah, arow0, K, p * BKc, tid);
        cp_tile_a(st + MATB_A,              Al, arow0, K, p * BKc, tid);
        cp_tile_b(st + 2 * MATB_A,          Bh, bcol0, N, p * BKc, tid);
        cp_tile_b(st + 2 * MATB_A + MATB_B, Bl, bcol0, N, p * BKc, tid);
        CP_COMMIT();
    }

    int stage = 0, pstage = 2;   // fill target = stage computed last iteration
    for (int kc = 0; kc < nk; ++kc) {
        if (kc + 1 < nk) { CP_WAIT(1); } else { CP_WAIT(0); }
        __syncthreads();   // single barrier: fences prior compute + fill visibility

        if (kc + 2 < nk) {
            uint32_t st = sb + (uint32_t)(pstage * STAGEB);
            const int k0 = (kc + 2) * BKc;
            cp_tile_a(st,                       Ah, arow0, K, k0, tid);
            cp_tile_a(st + MATB_A,              Al, arow0, K, k0, tid);
            cp_tile_b(st + 2 * MATB_A,          Bh, bcol0, N, k0, tid);
            cp_tile_b(st + 2 * MATB_A + MATB_B, Bl, bcol0, N, k0, tid);
            CP_COMMIT();
        }

        const uint32_t st = sb + (uint32_t)(stage * STAGEB);
        const uint32_t aH = st + a_off;
        const uint32_t aL = st + MATB_A + a_off;
        const uint32_t bH = st + 2 * MATB_A + b_off;
        const uint32_t bL = st + 2 * MATB_A + MATB_B + b_off;

#pragma unroll
        for (int ks = 0; ks < 2; ++ks) {
            const uint32_t ksoA = (uint32_t)(ks * 32);
            const uint32_t ksoB = (uint32_t)(ks * 16 * ROWB_B);
            uint32_t bh[4][2], bl[4][2];
#pragma unroll
            for (int j = 0; j < 2; j++) {
                uint32_t r[4];
                ldmx4t(r, bH + ksoB + (uint32_t)(j * 32));
                bh[2*j][0] = r[0]; bh[2*j][1] = r[1];
                bh[2*j+1][0] = r[2]; bh[2*j+1][1] = r[3];
                ldmx4t(r, bL + ksoB + (uint32_t)(j * 32));
                bl[2*j][0] = r[0]; bl[2*j][1] = r[1];
                bl[2*j+1][0] = r[2]; bl[2*j+1][1] = r[3];
            }
#pragma unroll
            for (int i = 0; i < 4; i++) {
                uint32_t ah[4], al[4];
                ldmx4(ah, aH + (uint32_t)(i * 16 * ROWB) + ksoA);
                ldmx4(al, aL + (uint32_t)(i * 16 * ROWB) + ksoA);
#pragma unroll
                for (int n = 0; n < 4; n++) mma_bf16(acc[i][n], ah, bh[n]);
#pragma unroll
                for (int n = 0; n < 4; n++) mma_bf16(acc[i][n], ah, bl[n]);
#pragma unroll
                for (int n = 0; n < 4; n++) mma_bf16(acc[i][n], al, bh[n]);
            }
        }
        stage = (stage == 2) ? 0 : stage + 1;
        pstage = (pstage == 2) ? 0 : pstage + 1;
    }

    const int gid = lane >> 2, tig = lane & 3;
#pragma unroll
    for (int i = 0; i < 4; i++) {
        const int r0 = by * 128 + wm * 64 + i * 16 + gid;
#pragma unroll
        for (int n = 0; n < 4; n++) {
            const int cg = bx * 128 + wn * 32 + n * 8 + tig * 2;
            const float b0 = bias[cg], b1 = bias[cg + 1];
            float v0 = acc[i][n][0] + b0;
            float v1 = acc[i][n][1] + b1;
            float v2 = acc[i][n][2] + b0;
            float v3 = acc[i][n][3] + b1;
            if (MODE & 1) {
                v0 = gelu_exact(v0); v1 = gelu_exact(v1);
                v2 = gelu_exact(v2); v3 = gelu_exact(v3);
            }
            if (MODE & 2) {
                const float* R0 = resid + (size_t)r0 * N + cg;
                const float* R1 = resid + (size_t)(r0 + 8) * N + cg;
                v0 += R0[0]; v1 += R0[1]; v2 += R1[0]; v3 += R1[1];
            }
            if (MODE & 4) {
                __nv_bfloat16 h0 = __float2bfloat16(v0), h1 = __float2bfloat16(v1);
                __nv_bfloat16 h2 = __float2bfloat16(v2), h3 = __float2bfloat16(v3);
                *(__nv_bfloat162*)(Ch + (size_t)r0 * N + cg)       = __nv_bfloat162(h0, h1);
                *(__nv_bfloat162*)(Ch + (size_t)(r0 + 8) * N + cg) = __nv_bfloat162(h2, h3);
                *(__nv_bfloat162*)(Cl + (size_t)r0 * N + cg) =
                    __nv_bfloat162(__float2bfloat16(v0 - __bfloat162float(h0)),
                                   __float2bfloat16(v1 - __bfloat162float(h1)));
                *(__nv_bfloat162*)(Cl + (size_t)(r0 + 8) * N + cg) =
                    __nv_bfloat162(__float2bfloat16(v2 - __bfloat162float(h2)),
                                   __float2bfloat16(v3 - __bfloat162float(h3)));
            } else {
                *(float2*)(C + (size_t)r0 * N + cg)       = make_float2(v0, v1);
                *(float2*)(C + (size_t)(r0 + 8) * N + cg) = make_float2(v2, v3);
            }
        }
    }
}

// ---------------- Flash attention via mma.sync (bf16 split) -----------------
#define FQH 0
#define FQL 16384
#define FKV0 32768
#define FMSK 98304
#define FSMEM 98816
#define SCL (0.125f * LOG2E)

__device__ __forceinline__ void fa_cp_kv(uint32_t sbase, const __nv_bfloat16* __restrict__ src,
                                         size_t gbase, int krow0, int tid) {
#pragma unroll
    for (int j = 0; j < 2; j++) {
        int e = tid + j * 256;
        int r = e >> 3, c = e & 7;
        uint32_t so = sbase + (uint32_t)(r * 128 + ((c ^ (r & 7)) * 16));
        const void* g = src + gbase + (size_t)(krow0 + r) * QKVW + c * 8;
        CP16(so, g);
    }
}

__global__ __launch_bounds__(256, 2)
void flashmma_kernel(const __nv_bfloat16* __restrict__ QKVh,
                     const __nv_bfloat16* __restrict__ QKVl,
                     const float* __restrict__ mask,
                     __nv_bfloat16* __restrict__ Ch, __nv_bfloat16* __restrict__ Cl) {
    extern __shared__ char sm[];
    const uint32_t sb = smem_u32(sm);
    const int tid = threadIdx.x, l = tid & 31, w = tid >> 5;
    const int gid = l >> 2, tig = l & 3;
    const int qt = blockIdx.x, h = blockIdx.y, b = blockIdx.z;
    const size_t gq = (size_t)b * Sn * QKVW + (size_t)h * DHn;
    const size_t gk = gq + Hn;
    const size_t gv = gq + 2 * Hn;
    const int qrow0 = qt * 128;

#pragma unroll
    for (int j = 0; j < 4; j++) {
        int e = tid + j * 256;
        int r = e >> 3, c = e & 7;
        uint32_t sw = (uint32_t)(r * 128 + ((c ^ (r & 7)) * 16));
        size_t g = gq + (size_t)(qrow0 + r) * QKVW + c * 8;
        CP16(sb + FQH + sw, QKVh + g);
        CP16(sb + FQL + sw, QKVl + g);
    }
    {
        uint32_t st = sb + FKV0;
        fa_cp_kv(st,         QKVh, gk, 0, tid);
        fa_cp_kv(st + 8192,  QKVl, gk, 0, tid);
        fa_cp_kv(st + 16384, QKVh, gv, 0, tid);
        fa_cp_kv(st + 24576, QKVl, gv, 0, tid);
        if (tid < 16) CP16(sb + FMSK + tid * 16, mask + b * Sn + tid * 4);
    }
    CP_COMMIT();

    float m0 = -1e30f, m1 = -1e30f, li0 = 0.f, li1 = 0.f;
    float o[8][4];
#pragma unroll
    for (int j = 0; j < 8; j++)
#pragma unroll
        for (int t = 0; t < 4; t++) o[j][t] = 0.f;

    const int rowq = w * 16 + (l & 15);
    const uint32_t qbaseH = sb + FQH + (uint32_t)(rowq * 128);
    const int rq7 = rowq & 7;
    const int qsel = l >> 4;

    for (int kt = 0; kt < Sn / 64; ++kt) {
        const int s = kt & 1;
        if (kt + 1 < Sn / 64) {
            uint32_t st = sb + FKV0 + (uint32_t)((s ^ 1) * 32768);
            fa_cp_kv(st,         QKVh, gk, (kt + 1) * 64, tid);
            fa_cp_kv(st + 8192,  QKVl, gk, (kt + 1) * 64, tid);
            fa_cp_kv(st + 16384, QKVh, gv, (kt + 1) * 64, tid);
            fa_cp_kv(st + 24576, QKVl, gv, (kt + 1) * 64, tid);
            if (tid < 16)
                CP16(sb + FMSK + (uint32_t)((s ^ 1) * 256 + tid * 16),
                     mask + b * Sn + (kt + 1) * 64 + tid * 4);
            CP_COMMIT();
            CP_WAIT(1);
        } else {
            CP_WAIT(0);
        }
        __syncthreads();

        const uint32_t stK = sb + FKV0 + (uint32_t)(s * 32768);

        float sc[8][4];
#pragma unroll
        for (int j = 0; j < 8; j++)
#pragma unroll
            for (int t = 0; t < 4; t++) sc[j][t] = 0.f;

#pragma unroll
        for (int kc = 0; kc < 4; ++kc) {
            uint32_t aH[4], aL[4];
            uint32_t qa = qbaseH + (uint32_t)((((2 * kc + qsel)) ^ rq7) * 16);
            ldmx4(aH, qa);
            ldmx4(aL, qa + 16384);
#pragma unroll
            for (int j = 0; j < 4; ++j) {
                int rowk = j * 16 + (l & 7) + ((l & 16) >> 1);
                uint32_t ka = stK + (uint32_t)(rowk * 128 +
                              (((2 * kc + ((l & 8) >> 3)) ^ (rowk & 7)) * 16));
                uint32_t bH[4], bL[4];
                ldmx4(bH, ka);
                ldmx4(bL, ka + 8192);
                mma_bf16(sc[2*j],   aH, bH);
                mma_bf16(sc[2*j+1], aH, bH + 2);
                mma_bf16(sc[2*j],   aH, bL);
                mma_bf16(sc[2*j+1], aH, bL + 2);
                mma_bf16(sc[2*j],   aL, bH);
                mma_bf16(sc[2*j+1], aL, bH + 2);
            }
        }

        const float* mk = (const float*)(sm + FMSK + s * 256);
        float tmax0 = -1e30f, tmax1 = -1e30f;
#pragma unroll
        for (int j = 0; j < 8; ++j) {
            float mL0 = mk[j * 8 + 2 * tig] * LOG2E;
            float mL1 = mk[j * 8 + 2 * tig + 1] * LOG2E;
            sc[j][0] = fmaf(sc[j][0], SCL, mL0);
            sc[j][1] = fmaf(sc[j][1], SCL, mL1);
            sc[j][2] = fmaf(sc[j][2], SCL, mL0);
            sc[j][3] = fmaf(sc[j][3], SCL, mL1);
            tmax0 = fmaxf(tmax0, fmaxf(sc[j][0], sc[j][1]));
            tmax1 = fmaxf(tmax1, fmaxf(sc[j][2], sc[j][3]));
        }
        tmax0 = fmaxf(tmax0, __shfl_xor_sync(0xffffffffu, tmax0, 1));
        tmax0 = fmaxf(tmax0, __shfl_xor_sync(0xffffffffu, tmax0, 2));
        tmax1 = fmaxf(tmax1, __shfl_xor_sync(0xffffffffu, tmax1, 1));
        tmax1 = fmaxf(tmax1, __shfl_xor_sync(0xffffffffu, tmax1, 2));
        float mn0 = fmaxf(m0, tmax0), mn1 = fmaxf(m1, tmax1);
        float a0 = exp2f(m0 - mn0), a1 = exp2f(m1 - mn1);
        m0 = mn0; m1 = mn1;
        float rs0 = 0.f, rs1 = 0.f;
#pragma unroll
        for (int j = 0; j < 8; ++j) {
            sc[j][0] = exp2f(sc[j][0] - mn0);
            sc[j][1] = exp2f(sc[j][1] - mn0);
            sc[j][2] = exp2f(sc[j][2] - mn1);
            sc[j][3] = exp2f(sc[j][3] - mn1);
            rs0 += sc[j][0] + sc[j][1];
            rs1 += sc[j][2] + sc[j][3];
        }
        rs0 += __shfl_xor_sync(0xffffffffu, rs0, 1);
        rs0 += __shfl_xor_sync(0xffffffffu, rs0, 2);
        rs1 += __shfl_xor_sync(0xffffffffu, rs1, 1);
        rs1 += __shfl_xor_sync(0xffffffffu, rs1, 2);
        li0 = li0 * a0 + rs0;
        li1 = li1 * a1 + rs1;
#pragma unroll
        for (int j = 0; j < 8; ++j) {
            o[j][0] *= a0; o[j][1] *= a0; o[j][2] *= a1; o[j][3] *= a1;
        }

        const uint32_t stV = stK + 16384;
#pragma unroll
        for (int kc = 0; kc < 4; ++kc) {
            uint32_t paH[4], paL[4];
#pragma unroll
            for (int q2 = 0; q2 < 2; ++q2) {
                const float* pp = sc[2 * kc + q2];
                __nv_bfloat16 h0 = __float2bfloat16(pp[0]);
                __nv_bfloat16 h1 = __float2bfloat16(pp[1]);
                __nv_bfloat16 h2 = __float2bfloat16(pp[2]);
                __nv_bfloat16 h3 = __float2bfloat16(pp[3]);
                __nv_bfloat162 ph01(h0, h1), ph23(h2, h3);
                paH[2 * q2]     = *(uint32_t*)&ph01;
                paH[2 * q2 + 1] = *(uint32_t*)&ph23;
                __nv_bfloat162 pl01(__float2bfloat16(pp[0] - __bfloat162float(h0)),
                                    __float2bfloat16(pp[1] - __bfloat162float(h1)));
                __nv_bfloat162 pl23(__float2bfloat16(pp[2] - __bfloat162float(h2)),
                                    __float2bfloat16(pp[3] - __bfloat162float(h3)));
                paL[2 * q2]     = *(uint32_t*)&pl01;
                paL[2 * q2 + 1] = *(uint32_t*)&pl23;
            }
#pragma unroll
            for (int jd = 0; jd < 4; ++jd) {
                int rowv = kc * 16 + (l & 15);
                uint32_t va = stV + (uint32_t)(rowv * 128 +
                              (((2 * jd + (l >> 4)) ^ (rowv & 7)) * 16));
                uint32_t bvH[4], bvL[4];
                ldmx4t(bvH, va);
                ldmx4t(bvL, va + 8192);
                mma_bf16(o[2*jd],   paH, bvH);
                mma_bf16(o[2*jd+1], paH, bvH + 2);
                mma_bf16(o[2*jd],   paH, bvL);
                mma_bf16(o[2*jd+1], paH, bvL + 2);
                mma_bf16(o[2*jd],   paL, bvH);
                mma_bf16(o[2*jd+1], paL, bvH + 2);
            }
        }
        __syncthreads();
    }

    const float i0 = 1.f / li0, i1 = 1.f / li1;
    const size_t gctx = (size_t)b * Sn * Hn + (size_t)h * DHn;
    const size_t r0o = gctx + (size_t)(qrow0 + w * 16 + gid) * Hn;
    const size_t r1o = r0o + (size_t)8 * Hn;
#pragma unroll
    for (int j = 0; j < 8; ++j) {
        int col = j * 8 + 2 * tig;
        float v0 = o[j][0] * i0, v1 = o[j][1] * i0;
        float v2 = o[j][2] * i1, v3 = o[j][3] * i1;
        __nv_bfloat16 h0 = __float2bfloat16(v0), h1 = __float2bfloat16(v1);
        __nv_bfloat16 h2 = __float2bfloat16(v2), h3 = __float2bfloat16(v3);
        *(__nv_bfloat162*)(Ch + r0o + col) = __nv_bfloat162(h0, h1);
        *(__nv_bfloat162*)(Ch + r1o + col) = __nv_bfloat162(h2, h3);
        *(__nv_bfloat162*)(Cl + r0o + col) =
            __nv_bfloat162(__float2bfloat16(v0 - __bfloat162float(h0)),
                           __float2bfloat16(v1 - __bfloat162float(h1)));
        *(__nv_bfloat162*)(Cl + r1o + col) =
            __nv_bfloat162(__float2bfloat16(v2 - __bfloat162float(h2)),
                           __float2bfloat16(v3 - __bfloat162float(h3)));
    }
}

// ---------------- LayerNorm over last dim (1024), optional split out --------
template <int SPLIT>
__global__ __launch_bounds__(256)
void ln_kernel(const float* __restrict__ X, const float* __restrict__ gam,
               const float* __restrict__ bet, float* __restrict__ Y,
               __nv_bfloat16* __restrict__ Yh, __nv_bfloat16* __restrict__ Yl) {
    const int row = blockIdx.x;
    const int tid = threadIdx.x;
    const float4 v = ((const float4*)(X + (size_t)row * Hn))[tid];
    float s  = v.x + v.y + v.z + v.w;
    float ss = v.x * v.x + v.y * v.y + v.z * v.z + v.w * v.w;
#pragma unroll
    for (int o = 16; o > 0; o >>= 1) {
        s  += __shfl_xor_sync(0xffffffffu, s, o);
        ss += __shfl_xor_sync(0xffffffffu, ss, o);
    }
    __shared__ float sh_s[8], sh_ss[8];
    const int wid = tid >> 5, lane = tid & 31;
    if (lane == 0) { sh_s[wid] = s; sh_ss[wid] = ss; }
    __syncthreads();
    s = 0.f; ss = 0.f;
#pragma unroll
    for (int i = 0; i < 8; i++) { s += sh_s[i]; ss += sh_ss[i]; }
    const float mean = s * (1.0f / Hn);
    const float var  = ss * (1.0f / Hn) - mean * mean;
    const float rstd = rsqrtf(var + 1e-5f);
    const float4 gv = ((const float4*)gam)[tid];
    const float4 bv = ((const float4*)bet)[tid];
    float4 out;
    out.x = (v.x - mean) * rstd * gv.x + bv.x;
    out.y = (v.y - mean) * rstd * gv.y + bv.y;
    out.z = (v.z - mean) * rstd * gv.z + bv.z;
    out.w = (v.w - mean) * rstd * gv.w + bv.w;
    ((float4*)(Y + (size_t)row * Hn))[tid] = out;
    if (SPLIT) {
        __nv_bfloat16 h0 = __float2bfloat16(out.x), h1 = __float2bfloat16(out.y);
        __nv_bfloat16 h2 = __float2bfloat16(out.z), h3 = __float2bfloat16(out.w);
        size_t base2 = (size_t)row * (Hn / 2) + tid * 2;
        ((__nv_bfloat162*)Yh)[base2]     = __nv_bfloat162(h0, h1);
        ((__nv_bfloat162*)Yh)[base2 + 1] = __nv_bfloat162(h2, h3);
        ((__nv_bfloat162*)Yl)[base2] =
            __nv_bfloat162(__float2bfloat16(out.x - __bfloat162float(h0)),
                           __float2bfloat16(out.y - __bfloat162float(h1)));
        ((__nv_bfloat162*)Yl)[base2 + 1] =
            __nv_bfloat162(__float2bfloat16(out.z - __bfloat162float(h2)),
                           __float2bfloat16(out.w - __bfloat162float(h3)));
    }
}

// ---------------- launch ----------------------------------------------------
static float* symaddrf(const void* sym) {
    void* p = nullptr;
    cudaGetSymbolAddress(&p, sym);
    return (float*)p;
}
static __nv_bfloat16* symaddrb(const void* sym) {
    void* p = nullptr;
    cudaGetSymbolAddress(&p, sym);
    return (__nv_bfloat16*)p;
}

extern "C" void kernel_launch(void* const* d_in, const int* in_sizes, int n_in,
                              void* d_out, int out_size) {
    const float* hidden = (const float*)d_in[0];
    const float* mask   = (const float*)d_in[1];
    const float* Wq = (const float*)d_in[2];  const float* bq = (const float*)d_in[3];
    const float* Wk = (const float*)d_in[4];  const float* bk = (const float*)d_in[5];
    const float* Wv = (const float*)d_in[6];  const float* bv = (const float*)d_in[7];
    const float* Wao= (const float*)d_in[8];  const float* bao= (const float*)d_in[9];
    const float* g1 = (const float*)d_in[10]; const float* b1 = (const float*)d_in[11];
    const float* Wi = (const float*)d_in[12]; const float* bi = (const float*)d_in[13];
    const float* Wo = (const float*)d_in[14]; const float* bo = (const float*)d_in[15];
    const float* g2 = (const float*)d_in[16]; const float* b2 = (const float*)d_in[17];
    float* outp = (float*)d_out;

    float* y  = symaddrf(g_y);
    float* x1 = symaddrf(g_x1);
    float* x2 = symaddrf(g_x2);
    float* bqkv = symaddrf(g_bqkv);
    __nv_bfloat16* xh  = symaddrb(g_xh);  __nv_bfloat16* xl  = symaddrb(g_xl);
    __nv_bfloat16* qkvh = symaddrb(g_qkvh); __nv_bfloat16* qkvl = symaddrb(g_qkvl);
    __nv_bfloat16* cxh = symaddrb(g_cxh); __nv_bfloat16* cxl = symaddrb(g_cxl);
    __nv_bfloat16* fh  = symaddrb(g_fh);  __nv_bfloat16* fl  = symaddrb(g_fl);
    __nv_bfloat16* wth = symaddrb(g_wth); __nv_bfloat16* wtl = symaddrb(g_wtl);

    cudaFuncSetAttribute(flashmma_kernel, cudaFuncAttributeMaxDynamicSharedMemorySize, FSMEM);
    cudaFuncSetAttribute(bgemm_kernel<4>,  cudaFuncAttributeMaxDynamicSharedMemorySize, GSMEM);
    cudaFuncSetAttribute(bgemm_kernel<2>,  cudaFuncAttributeMaxDynamicSharedMemorySize, GSMEM);
    cudaFuncSetAttribute(bgemm_kernel<5>,  cudaFuncAttributeMaxDynamicSharedMemorySize, GSMEM);

    // ---- fused weight prep: ONE launch for all 12 matrices ----
    const int n4_hh = Hn * Hn / 4;
    const int n4_hf = Hn * FFn / 4;
    WSegTable T;
    {
        int c = 0, s = 0;
        for (int l = 0; l < Lnum; ++l) {
            const long long wb = (long long)l * LW_ELEMS;
            T.src[s] = Wq + (size_t)l*Hn*Hn; T.N[s] = Hn;  T.LD[s] = QKVW; T.OFF[s] = 0;
            T.dst[s] = wb + LW_QKV; T.cum[s] = c; c += n4_hh; s++;
            T.src[s] = Wk + (size_t)l*Hn*Hn; T.N[s] = Hn;  T.LD[s] = QKVW; T.OFF[s] = Hn;
            T.dst[s] = wb + LW_QKV; T.cum[s] = c; c += n4_hh; s++;
            T.src[s] = Wv + (size_t)l*Hn*Hn; T.N[s] = Hn;  T.LD[s] = QKVW; T.OFF[s] = 2*Hn;
            T.dst[s] = wb + LW_QKV; T.cum[s] = c; c += n4_hh; s++;
            T.src[s] = Wao+ (size_t)l*Hn*Hn; T.N[s] = Hn;  T.LD[s] = Hn;   T.OFF[s] = 0;
            T.dst[s] = wb + LW_AO;  T.cum[s] = c; c += n4_hh; s++;
            T.src[s] = Wi + (size_t)l*Hn*FFn; T.N[s] = FFn; T.LD[s] = FFn; T.OFF[s] = 0;
            T.dst[s] = wb + LW_I;   T.cum[s] = c; c += n4_hf; s++;
            T.src[s] = Wo + (size_t)l*FFn*Hn; T.N[s] = Hn;  T.LD[s] = Hn;  T.OFF[s] = 0;
            T.dst[s] = wb + LW_O;   T.cum[s] = c; c += n4_hf; s++;
        }
        T.cum[NSEG] = c;
    }
    wsplit_all_kernel<<<1184, 256>>>(T, wth, wtl);
    bconcat_kernel<<<(Lnum * QKVW + 255) / 256, 256>>>(bq, bk, bv, bqkv);
    split_kernel<<<Mrows * Hn / 1024, 256>>>(hidden, xh, xl, Mrows * Hn / 4);

    const dim3 gQKV(QKVW / 128, Mrows / 128);  // (24, 32)
    const dim3 gAO (Hn / 128,  Mrows / 128);   // (8, 32)
    const dim3 gFF1(FFn / 128, Mrows / 128);   // (32, 32)
    const dim3 gFA(Sn / 128, NHn, Bn);         // (16, 16, 2)

    for (int l = 0; l < Lnum; ++l) {
        const float* xf = (l == 0) ? hidden : x2;
        const size_t wb  = (size_t)l * LW_ELEMS;
        const size_t bo1 = (size_t)l * Hn;
        const size_t bio = (size_t)l * FFn;

        bgemm_kernel<4><<<gQKV, 256, GSMEM>>>(xh, xl, wth + wb + LW_QKV, wtl + wb + LW_QKV,
                                              bqkv + (size_t)l*QKVW, nullptr, nullptr,
                                              qkvh, qkvl, Hn, QKVW);

        flashmma_kernel<<<gFA, 256, FSMEM>>>(qkvh, qkvl, mask, cxh, cxl);

        bgemm_kernel<2><<<gAO, 256, GSMEM>>>(cxh, cxl, wth + wb + LW_AO, wtl + wb + LW_AO,
                                             bao + bo1, xf, y, nullptr, nullptr, Hn, Hn);
        ln_kernel<1><<<Mrows, 256>>>(y, g1 + bo1, b1 + bo1, x1, xh, xl);

        bgemm_kernel<5><<<gFF1, 256, GSMEM>>>(xh, xl, wth + wb + LW_I, wtl + wb + LW_I,
                                              bi + bio, nullptr, nullptr, fh, fl, Hn, FFn);
        bgemm_kernel<2><<<gAO, 256, GSMEM>>>(fh, fl, wth + wb + LW_O, wtl + wb + LW_O,
                                             bo + bo1, x1, y, nullptr, nullptr, FFn, Hn);
        if (l == Lnum - 1)
            ln_kernel<0><<<Mrows, 256>>>(y, g2 + bo1, b2 + bo1, outp, nullptr, nullptr);
        else
            ln_kernel<1><<<Mrows, 256>>>(y, g2 + bo1, b2 + bo1, x2, xh, xl);
    }
}

// round 15
// speedup vs baseline: 1.0702x; 1.0702x over previous
#include <cuda_runtime.h>
#include <cuda_bf16.h>
#include <math.h>
#include <stdint.h>

// Problem constants
#define Lnum 2
#define Bn   2
#define Sn   2048
#define Hn   1024
#define NHn  16
#define DHn  64
#define FFn  4096
#define Mrows (Bn*Sn)   // 4096
#define QKVW 3072

#define LOG2E 1.4426950408889634f

// ---------------- scratch (device globals; no allocation allowed) ----------
__device__ float g_y  [Mrows*Hn];
__device__ float g_x1 [Mrows*Hn];
__device__ float g_x2 [Mrows*Hn];
__device__ float g_bqkv[Lnum*QKVW];

__device__ __nv_bfloat16 g_xh[Mrows*Hn],  g_xl[Mrows*Hn];
__device__ __nv_bfloat16 g_qkvh[(size_t)Mrows*QKVW], g_qkvl[(size_t)Mrows*QKVW];
__device__ __nv_bfloat16 g_cxh[Mrows*Hn], g_cxl[Mrows*Hn];
__device__ __nv_bfloat16 g_fh[(size_t)Mrows*FFn], g_fl[(size_t)Mrows*FFn];

// K-major split weights per layer: [QKV fused 1024x3072 | AO 1024x1024 | WI 1024x4096 | WO 4096x1024]
#define LW_QKV 0
#define LW_AO  3145728
#define LW_I   4194304
#define LW_O   8388608
#define LW_ELEMS 12582912
__device__ __nv_bfloat16 g_wth[(size_t)Lnum*LW_ELEMS];
__device__ __nv_bfloat16 g_wtl[(size_t)Lnum*LW_ELEMS];

// ---------------- PTX helpers (sm_80-era ISA only) ---------------------------
__device__ __forceinline__ uint32_t smem_u32(const void* p) {
    uint32_t a;
    asm("{ .reg .u64 t; cvta.to.shared.u64 t, %1; cvt.u32.u64 %0, t; }" : "=r"(a) : "l"(p));
    return a;
}
__device__ __forceinline__ void ldmx4(uint32_t* r, uint32_t addr) {
    asm volatile("ldmatrix.sync.aligned.m8n8.x4.shared.b16 {%0,%1,%2,%3}, [%4];"
                 : "=r"(r[0]), "=r"(r[1]), "=r"(r[2]), "=r"(r[3]) : "r"(addr));
}
__device__ __forceinline__ void ldmx4t(uint32_t* r, uint32_t addr) {
    asm volatile("ldmatrix.sync.aligned.m8n8.x4.trans.shared.b16 {%0,%1,%2,%3}, [%4];"
                 : "=r"(r[0]), "=r"(r[1]), "=r"(r[2]), "=r"(r[3]) : "r"(addr));
}
__device__ __forceinline__ void mma_bf16(float* c, const uint32_t* a, const uint32_t* b) {
    asm volatile(
        "mma.sync.aligned.m16n8k16.row.col.f32.bf16.bf16.f32 "
        "{%0,%1,%2,%3}, {%4,%5,%6,%7}, {%8,%9}, {%0,%1,%2,%3};"
        : "+f"(c[0]), "+f"(c[1]), "+f"(c[2]), "+f"(c[3])
        : "r"(a[0]), "r"(a[1]), "r"(a[2]), "r"(a[3]), "r"(b[0]), "r"(b[1]));
}
#define CP_COMMIT() asm volatile("cp.async.commit_group;" ::: "memory")
#define CP_WAIT(N)  asm volatile("cp.async.wait_group %0;" :: "n"(N) : "memory")
#define CP16(so, g) asm volatile("cp.async.ca.shared.global [%0], [%1], 16;" :: "r"(so), "l"(g))

// ---------------- conversion kernels ----------------------------------------
__global__ __launch_bounds__(256)
void split_kernel(const float* __restrict__ x, __nv_bfloat16* __restrict__ h,
                  __nv_bfloat16* __restrict__ l, int n4) {
    int i = blockIdx.x * 256 + threadIdx.x;
    if (i >= n4) return;
    float4 v = ((const float4*)x)[i];
    __nv_bfloat16 h0 = __float2bfloat16(v.x);
    __nv_bfloat16 h1 = __float2bfloat16(v.y);
    __nv_bfloat16 h2 = __float2bfloat16(v.z);
    __nv_bfloat16 h3 = __float2bfloat16(v.w);
    ((__nv_bfloat162*)h)[2*i]   = __nv_bfloat162(h0, h1);
    ((__nv_bfloat162*)h)[2*i+1] = __nv_bfloat162(h2, h3);
    ((__nv_bfloat162*)l)[2*i]   = __nv_bfloat162(__float2bfloat16(v.x - __bfloat162float(h0)),
                                                 __float2bfloat16(v.y - __bfloat162float(h1)));
    ((__nv_bfloat162*)l)[2*i+1] = __nv_bfloat162(__float2bfloat16(v.z - __bfloat162float(h2)),
                                                 __float2bfloat16(v.w - __bfloat162float(h3)));
}

// bias concat for BOTH layers
__global__ __launch_bounds__(256)
void bconcat_kernel(const float* __restrict__ bq, const float* __restrict__ bk,
                    const float* __restrict__ bv, float* __restrict__ out) {
    int i = blockIdx.x * 256 + threadIdx.x;
    if (i >= Lnum * QKVW) return;
    int l = i / QKVW, j = i - l * QKVW;
    float v = (j < Hn) ? bq[l * Hn + j]
             : ((j < 2 * Hn) ? bk[l * Hn + j - Hn] : bv[l * Hn + j - 2 * Hn]);
    out[i] = v;
}

// Fused weight split: ALL 12 weight matrices in one launch.
#define NSEG 12
struct WSegTable {
    const float* src[NSEG];
    int N[NSEG], LD[NSEG], OFF[NSEG];
    long long dst[NSEG];
    int cum[NSEG + 1];
};

__global__ __launch_bounds__(256)
void wsplit_all_kernel(WSegTable T, __nv_bfloat16* __restrict__ th,
                       __nv_bfloat16* __restrict__ tl) {
    const int total = T.cum[NSEG];
    for (int i = blockIdx.x * 256 + threadIdx.x; i < total; i += gridDim.x * 256) {
        int s = 0;
#pragma unroll
        for (int j = 1; j < NSEG; j++) s += (i >= T.cum[j]);
        const int i4 = i - T.cum[s];
        const int idx = i4 * 4;
        const int N = T.N[s];
        const int k = idx / N, n = idx - k * N;
        float4 v = *(const float4*)(T.src[s] + idx);
        const size_t o = (size_t)T.dst[s] + (size_t)k * T.LD[s] + T.OFF[s] + n;
        __nv_bfloat16 h0 = __float2bfloat16(v.x);
        __nv_bfloat16 h1 = __float2bfloat16(v.y);
        __nv_bfloat16 h2 = __float2bfloat16(v.z);
        __nv_bfloat16 h3 = __float2bfloat16(v.w);
        *(__nv_bfloat162*)(th + o)     = __nv_bfloat162(h0, h1);
        *(__nv_bfloat162*)(th + o + 2) = __nv_bfloat162(h2, h3);
        *(__nv_bfloat162*)(tl + o) =
            __nv_bfloat162(__float2bfloat16(v.x - __bfloat162float(h0)),
                           __float2bfloat16(v.y - __bfloat162float(h1)));
        *(__nv_bfloat162*)(tl + o + 2) =
            __nv_bfloat162(__float2bfloat16(v.z - __bfloat162float(h2)),
                           __float2bfloat16(v.w - __bfloat162float(h3)));
    }
}

// ---------------- bf16-split GEMM via mma.sync (HMMA) -----------------------
// R11 config (measured local optimum): 128x128 CTA, 256 threads (8 warps =
// 2M x 4N, warp tile 64x32), BK=32, 2-stage cp.async (.ca), 2 CTAs/SM.
// A [M,K] row-major hi/lo; B [K,N] K-major hi/lo (ldmatrix.trans fragments).
// MODE bits: 1=gelu, 2=resid, 4=split-out (bf16 hi/lo)
#define BKc 32
#define ROWB 80
#define ROWB_B 272
#define MATB_A (128*ROWB)            // 10240
#define MATB_B (32*ROWB_B)           // 8704
#define STAGEB (2*MATB_A + 2*MATB_B) // 37888
#define GSMEM (2*STAGEB)             // 75776

__device__ __forceinline__ float gelu_exact(float x) {
    return 0.5f * x * (1.0f + erff(x * 0.7071067811865475f));
}

// A tile 128x32 bf16 = 512 16B chunks; 2 iters
__device__ __forceinline__ void cp_tile_a(uint32_t sdst, const __nv_bfloat16* __restrict__ src,
                                          int row0, int K, int k0, int tid) {
#pragma unroll
    for (int j = 0; j < 2; j++) {
        int e = tid + j * 256;
        int r = e >> 2, c = e & 3;
        uint32_t so = sdst + (uint32_t)(r * ROWB + c * 16);
        const void* g = src + (size_t)(row0 + r) * K + k0 + c * 8;
        CP16(so, g);
    }
}
// B tile 32x128 bf16 (K-major rows of 256B) = 512 16B chunks; 2 iters
__device__ __forceinline__ void cp_tile_b(uint32_t sdst, const __nv_bfloat16* __restrict__ src,
                                          int n0, int N, int k0, int tid) {
#pragma unroll
    for (int j = 0; j < 2; j++) {
        int e = tid + j * 256;
        int r = e >> 4, c = e & 15;
        uint32_t so = sdst + (uint32_t)(r * ROWB_B + c * 16);
        const void* g = src + (size_t)(k0 + r) * N + n0 + c * 8;
        CP16(so, g);
    }
}

template <int MODE>
__global__ __launch_bounds__(256, 2)
void bgemm_kernel(const __nv_bfloat16* __restrict__ Ah, const __nv_bfloat16* __restrict__ Al,
                  const __nv_bfloat16* __restrict__ Bh, const __nv_bfloat16* __restrict__ Bl,
                  const float* __restrict__ bias, const float* __restrict__ resid,
                  float* __restrict__ C, __nv_bfloat16* __restrict__ Ch,
                  __nv_bfloat16* __restrict__ Cl, int K, int N) {
    extern __shared__ char smem_raw[];
    const uint32_t sb = smem_u32(smem_raw);

    const int tid = threadIdx.x;
    const int lane = tid & 31, wid = tid >> 5;
    const int wm = wid >> 2, wn = wid & 3;    // 2M x 4N warps; warp tile 64x32
    const int bx = blockIdx.x, by = blockIdx.y;
    const int arow0 = by * 128, bcol0 = bx * 128;

    float acc[4][4][4];
#pragma unroll
    for (int i = 0; i < 4; i++)
#pragma unroll
        for (int n = 0; n < 4; n++)
#pragma unroll
            for (int t = 0; t < 4; t++) acc[i][n][t] = 0.f;

    const uint32_t a_off = (uint32_t)((wm * 64 + (lane & 15)) * ROWB + ((lane & 16) ? 16 : 0));
    const uint32_t b_off = (uint32_t)((lane & 15) * ROWB_B + wn * 64 + ((lane & 16) ? 16 : 0));

    const int nk = K / BKc;

    {   // prologue: stage 0
        cp_tile_a(sb,                       Ah, arow0, K, 0, tid);
        cp_tile_a(sb + MATB_A,              Al, arow0, K, 0, tid);
        cp_tile_b(sb + 2 * MATB_A,          Bh, bcol0, N, 0, tid);
        cp_tile_b(sb + 2 * MATB_A + MATB_B, Bl, bcol0, N, 0, tid);
        CP_COMMIT();
    }

    for (int kc = 0; kc < nk; ++kc) {
        const int s = kc & 1;
        if (kc + 1 < nk) {
            uint32_t st = sb + (uint32_t)(((kc + 1) & 1) * STAGEB);
            const int k0 = (kc + 1) * BKc;
            cp_tile_a(st,                       Ah, arow0, K, k0, tid);
            cp_tile_a(st + MATB_A,              Al, arow0, K, k0, tid);
            cp_tile_b(st + 2 * MATB_A,          Bh, bcol0, N, k0, tid);
            cp_tile_b(st + 2 * MATB_A + MATB_B, Bl, bcol0, N, k0, tid);
            CP_COMMIT();
            CP_WAIT(1);
        } else {
            CP_WAIT(0);
        }
        __syncthreads();

        const uint32_t st = sb + (uint32_t)(s * STAGEB);
        const uint32_t aH = st + a_off;
        const uint32_t aL = st + MATB_A + a_off;
        const uint32_t bH = st + 2 * MATB_A + b_off;
        const uint32_t bL = st + 2 * MATB_A + MATB_B + b_off;

#pragma unroll
        for (int ks = 0; ks < 2; ++ks) {
            const uint32_t ksoA = (uint32_t)(ks * 32);
            const uint32_t ksoB = (uint32_t)(ks * 16 * ROWB_B);
            uint32_t bh[4][2], bl[4][2];
#pragma unroll
            for (int j = 0; j < 2; j++) {
                uint32_t r[4];
                ldmx4t(r, bH + ksoB + (uint32_t)(j * 32));
                bh[2*j][0] = r[0]; bh[2*j][1] = r[1];
                bh[2*j+1][0] = r[2]; bh[2*j+1][1] = r[3];
                ldmx4t(r, bL + ksoB + (uint32_t)(j * 32));
                bl[2*j][0] = r[0]; bl[2*j][1] = r[1];
                bl[2*j+1][0] = r[2]; bl[2*j+1][1] = r[3];
            }
#pragma unroll
            for (int i = 0; i < 4; i++) {
                uint32_t ah[4], al[4];
                ldmx4(ah, aH + (uint32_t)(i * 16 * ROWB) + ksoA);
                ldmx4(al, aL + (uint32_t)(i * 16 * ROWB) + ksoA);
#pragma unroll
                for (int n = 0; n < 4; n++) mma_bf16(acc[i][n], ah, bh[n]);
#pragma unroll
                for (int n = 0; n < 4; n++) mma_bf16(acc[i][n], ah, bl[n]);
#pragma unroll
                for (int n = 0; n < 4; n++) mma_bf16(acc[i][n], al, bh[n]);
            }
        }
        __syncthreads();
    }

    const int gid = lane >> 2, tig = lane & 3;
    // hoist bias (depends only on n)
    float bsv0[4], bsv1[4];
#pragma unroll
    for (int n = 0; n < 4; n++) {
        const int cg = bx * 128 + wn * 32 + n * 8 + tig * 2;
        bsv0[n] = bias[cg];
        bsv1[n] = bias[cg + 1];
    }
#pragma unroll
    for (int i = 0; i < 4; i++) {
        const int r0 = by * 128 + wm * 64 + i * 16 + gid;
#pragma unroll
        for (int n = 0; n < 4; n++) {
            const int cg = bx * 128 + wn * 32 + n * 8 + tig * 2;
            float v0 = acc[i][n][0] + bsv0[n];
            float v1 = acc[i][n][1] + bsv1[n];
            float v2 = acc[i][n][2] + bsv0[n];
            float v3 = acc[i][n][3] + bsv1[n];
            if (MODE & 1) {
                v0 = gelu_exact(v0); v1 = gelu_exact(v1);
                v2 = gelu_exact(v2); v3 = gelu_exact(v3);
            }
            if (MODE & 2) {
                const float* R0 = resid + (size_t)r0 * N + cg;
                const float* R1 = resid + (size_t)(r0 + 8) * N + cg;
                v0 += R0[0]; v1 += R0[1]; v2 += R1[0]; v3 += R1[1];
            }
            if (MODE & 4) {
                __nv_bfloat16 h0 = __float2bfloat16(v0), h1 = __float2bfloat16(v1);
                __nv_bfloat16 h2 = __float2bfloat16(v2), h3 = __float2bfloat16(v3);
                *(__nv_bfloat162*)(Ch + (size_t)r0 * N + cg)       = __nv_bfloat162(h0, h1);
                *(__nv_bfloat162*)(Ch + (size_t)(r0 + 8) * N + cg) = __nv_bfloat162(h2, h3);
                *(__nv_bfloat162*)(Cl + (size_t)r0 * N + cg) =
                    __nv_bfloat162(__float2bfloat16(v0 - __bfloat162float(h0)),
                                   __float2bfloat16(v1 - __bfloat162float(h1)));
                *(__nv_bfloat162*)(Cl + (size_t)(r0 + 8) * N + cg) =
                    __nv_bfloat162(__float2bfloat16(v2 - __bfloat162float(h2)),
                                   __float2bfloat16(v3 - __bfloat162float(h3)));
            } else {
                *(float2*)(C + (size_t)r0 * N + cg)       = make_float2(v0, v1);
                *(float2*)(C + (size_t)(r0 + 8) * N + cg) = make_float2(v2, v3);
            }
        }
    }
}

// ---------------- Flash attention via mma.sync (bf16 split) -----------------
#define FQH 0
#define FQL 16384
#define FKV0 32768
#define FMSK 98304
#define FSMEM 98816
#define SCL (0.125f * LOG2E)

__device__ __forceinline__ void fa_cp_kv(uint32_t sbase, const __nv_bfloat16* __restrict__ src,
                                         size_t gbase, int krow0, int tid) {
#pragma unroll
    for (int j = 0; j < 2; j++) {
        int e = tid + j * 256;
        int r = e >> 3, c = e & 7;
        uint32_t so = sbase + (uint32_t)(r * 128 + ((c ^ (r & 7)) * 16));
        const void* g = src + gbase + (size_t)(krow0 + r) * QKVW + c * 8;
        CP16(so, g);
    }
}

__global__ __launch_bounds__(256, 2)
void flashmma_kernel(const __nv_bfloat16* __restrict__ QKVh,
                     const __nv_bfloat16* __restrict__ QKVl,
                     const float* __restrict__ mask,
                     __nv_bfloat16* __restrict__ Ch, __nv_bfloat16* __restrict__ Cl) {
    extern __shared__ char sm[];
    const uint32_t sb = smem_u32(sm);
    const int tid = threadIdx.x, l = tid & 31, w = tid >> 5;
    const int gid = l >> 2, tig = l & 3;
    const int qt = blockIdx.x, h = blockIdx.y, b = blockIdx.z;
    const size_t gq = (size_t)b * Sn * QKVW + (size_t)h * DHn;
    const size_t gk = gq + Hn;
    const size_t gv = gq + 2 * Hn;
    const int qrow0 = qt * 128;

#pragma unroll
    for (int j = 0; j < 4; j++) {
        int e = tid + j * 256;
        int r = e >> 3, c = e & 7;
        uint32_t sw = (uint32_t)(r * 128 + ((c ^ (r & 7)) * 16));
        size_t g = gq + (size_t)(qrow0 + r) * QKVW + c * 8;
        CP16(sb + FQH + sw, QKVh + g);
        CP16(sb + FQL + sw, QKVl + g);
    }
    {
        uint32_t st = sb + FKV0;
        fa_cp_kv(st,         QKVh, gk, 0, tid);
        fa_cp_kv(st + 8192,  QKVl, gk, 0, tid);
        fa_cp_kv(st + 16384, QKVh, gv, 0, tid);
        fa_cp_kv(st + 24576, QKVl, gv, 0, tid);
        if (tid < 16) CP16(sb + FMSK + tid * 16, mask + b * Sn + tid * 4);
    }
    CP_COMMIT();

    float m0 = -1e30f, m1 = -1e30f, li0 = 0.f, li1 = 0.f;
    float o[8][4];
#pragma unroll
    for (int j = 0; j < 8; j++)
#pragma unroll
        for (int t = 0; t < 4; t++) o[j][t] = 0.f;

    const int rowq = w * 16 + (l & 15);
    const uint32_t qbaseH = sb + FQH + (uint32_t)(rowq * 128);
    const int rq7 = rowq & 7;
    const int qsel = l >> 4;

    for (int kt = 0; kt < Sn / 64; ++kt) {
        const int s = kt & 1;
        if (kt + 1 < Sn / 64) {
            uint32_t st = sb + FKV0 + (uint32_t)((s ^ 1) * 32768);
            fa_cp_kv(st,         QKVh, gk, (kt + 1) * 64, tid);
            fa_cp_kv(st + 8192,  QKVl, gk, (kt + 1) * 64, tid);
            fa_cp_kv(st + 16384, QKVh, gv, (kt + 1) * 64, tid);
            fa_cp_kv(st + 24576, QKVl, gv, (kt + 1) * 64, tid);
            if (tid < 16)
                CP16(sb + FMSK + (uint32_t)((s ^ 1) * 256 + tid * 16),
                     mask + b * Sn + (kt + 1) * 64 + tid * 4);
            CP_COMMIT();
            CP_WAIT(1);
        } else {
            CP_WAIT(0);
        }
        __syncthreads();

        const uint32_t stK = sb + FKV0 + (uint32_t)(s * 32768);

        float sc[8][4];
#pragma unroll
        for (int j = 0; j < 8; j++)
#pragma unroll
            for (int t = 0; t < 4; t++) sc[j][t] = 0.f;

#pragma unroll
        for (int kc = 0; kc < 4; ++kc) {
            uint32_t aH[4], aL[4];
            uint32_t qa = qbaseH + (uint32_t)((((2 * kc + qsel)) ^ rq7) * 16);
            ldmx4(aH, qa);
            ldmx4(aL, qa + 16384);
#pragma unroll
            for (int j = 0; j < 4; ++j) {
                int rowk = j * 16 + (l & 7) + ((l & 16) >> 1);
                uint32_t ka = stK + (uint32_t)(rowk * 128 +
                              (((2 * kc + ((l & 8) >> 3)) ^ (rowk & 7)) * 16));
                uint32_t bH[4], bL[4];
                ldmx4(bH, ka);
                ldmx4(bL, ka + 8192);
                mma_bf16(sc[2*j],   aH, bH);
                mma_bf16(sc[2*j+1], aH, bH + 2);
                mma_bf16(sc[2*j],   aH, bL);
                mma_bf16(sc[2*j+1], aH, bL + 2);
                mma_bf16(sc[2*j],   aL, bH);
                mma_bf16(sc[2*j+1], aL, bH + 2);
            }
        }

        const float* mk = (const float*)(sm + FMSK + s * 256);
        float tmax0 = -1e30f, tmax1 = -1e30f;
#pragma unroll
        for (int j = 0; j < 8; ++j) {
            float mL0 = mk[j * 8 + 2 * tig] * LOG2E;
            float mL1 = mk[j * 8 + 2 * tig + 1] * LOG2E;
            sc[j][0] = fmaf(sc[j][0], SCL, mL0);
            sc[j][1] = fmaf(sc[j][1], SCL, mL1);
            sc[j][2] = fmaf(sc[j][2], SCL, mL0);
            sc[j][3] = fmaf(sc[j][3], SCL, mL1);
            tmax0 = fmaxf(tmax0, fmaxf(sc[j][0], sc[j][1]));
            tmax1 = fmaxf(tmax1, fmaxf(sc[j][2], sc[j][3]));
        }
        tmax0 = fmaxf(tmax0, __shfl_xor_sync(0xffffffffu, tmax0, 1));
        tmax0 = fmaxf(tmax0, __shfl_xor_sync(0xffffffffu, tmax0, 2));
        tmax1 = fmaxf(tmax1, __shfl_xor_sync(0xffffffffu, tmax1, 1));
        tmax1 = fmaxf(tmax1, __shfl_xor_sync(0xffffffffu, tmax1, 2));
        float mn0 = fmaxf(m0, tmax0), mn1 = fmaxf(m1, tmax1);
        float a0 = exp2f(m0 - mn0), a1 = exp2f(m1 - mn1);
        m0 = mn0; m1 = mn1;
        float rs0 = 0.f, rs1 = 0.f;
#pragma unroll
        for (int j = 0; j < 8; ++j) {
            sc[j][0] = exp2f(sc[j][0] - mn0);
            sc[j][1] = exp2f(sc[j][1] - mn0);
            sc[j][2] = exp2f(sc[j][2] - mn1);
            sc[j][3] = exp2f(sc[j][3] - mn1);
            rs0 += sc[j][0] + sc[j][1];
            rs1 += sc[j][2] + sc[j][3];
        }
        rs0 += __shfl_xor_sync(0xffffffffu, rs0, 1);
        rs0 += __shfl_xor_sync(0xffffffffu, rs0, 2);
        rs1 += __shfl_xor_sync(0xffffffffu, rs1, 1);
        rs1 += __shfl_xor_sync(0xffffffffu, rs1, 2);
        li0 = li0 * a0 + rs0;
        li1 = li1 * a1 + rs1;
#pragma unroll
        for (int j = 0; j < 8; ++j) {
            o[j][0] *= a0; o[j][1] *= a0; o[j][2] *= a1; o[j][3] *= a1;
        }

        const uint32_t stV = stK + 16384;
#pragma unroll
        for (int kc = 0; kc < 4; ++kc) {
            uint32_t paH[4], paL[4];
#pragma unroll
            for (int q2 = 0; q2 < 2; ++q2) {
                const float* pp = sc[2 * kc + q2];
                __nv_bfloat16 h0 = __float2bfloat16(pp[0]);
                __nv_bfloat16 h1 = __float2bfloat16(pp[1]);
                __nv_bfloat16 h2 = __float2bfloat16(pp[2]);
                __nv_bfloat16 h3 = __float2bfloat16(pp[3]);
                __nv_bfloat162 ph01(h0, h1), ph23(h2, h3);
                paH[2 * q2]     = *(uint32_t*)&ph01;
                paH[2 * q2 + 1] = *(uint32_t*)&ph23;
                __nv_bfloat162 pl01(__float2bfloat16(pp[0] - __bfloat162float(h0)),
                                    __float2bfloat16(pp[1] - __bfloat162float(h1)));
                __nv_bfloat162 pl23(__float2bfloat16(pp[2] - __bfloat162float(h2)),
                                    __float2bfloat16(pp[3] - __bfloat162float(h3)));
                paL[2 * q2]     = *(uint32_t*)&pl01;
                paL[2 * q2 + 1] = *(uint32_t*)&pl23;
            }
#pragma unroll
            for (int jd = 0; jd < 4; ++jd) {
                int rowv = kc * 16 + (l & 15);
                uint32_t va = stV + (uint32_t)(rowv * 128 +
                              (((2 * jd + (l >> 4)) ^ (rowv & 7)) * 16));
                uint32_t bvH[4], bvL[4];
                ldmx4t(bvH, va);
                ldmx4t(bvL, va + 8192);
                mma_bf16(o[2*jd],   paH, bvH);
                mma_bf16(o[2*jd+1], paH, bvH + 2);
                mma_bf16(o[2*jd],   paH, bvL);
                mma_bf16(o[2*jd+1], paH, bvL + 2);
                mma_bf16(o[2*jd],   paL, bvH);
                mma_bf16(o[2*jd+1], paL, bvH + 2);
            }
        }
        __syncthreads();
    }

    const float i0 = 1.f / li0, i1 = 1.f / li1;
    const size_t gctx = (size_t)b * Sn * Hn + (size_t)h * DHn;
    const size_t r0o = gctx + (size_t)(qrow0 + w * 16 + gid) * Hn;
    const size_t r1o = r0o + (size_t)8 * Hn;
#pragma unroll
    for (int j = 0; j < 8; ++j) {
        int col = j * 8 + 2 * tig;
        float v0 = o[j][0] * i0, v1 = o[j][1] * i0;
        float v2 = o[j][2] * i1, v3 = o[j][3] * i1;
        __nv_bfloat16 h0 = __float2bfloat16(v0), h1 = __float2bfloat16(v1);
        __nv_bfloat16 h2 = __float2bfloat16(v2), h3 = __float2bfloat16(v3);
        *(__nv_bfloat162*)(Ch + r0o + col) = __nv_bfloat162(h0, h1);
        *(__nv_bfloat162*)(Ch + r1o + col) = __nv_bfloat162(h2, h3);
        *(__nv_bfloat162*)(Cl + r0o + col) =
            __nv_bfloat162(__float2bfloat16(v0 - __bfloat162float(h0)),
                           __float2bfloat16(v1 - __bfloat162float(h1)));
        *(__nv_bfloat162*)(Cl + r1o + col) =
            __nv_bfloat162(__float2bfloat16(v2 - __bfloat162float(h2)),
                           __float2bfloat16(v3 - __bfloat162float(h3)));
    }
}

// ---------------- LayerNorm over last dim (1024), optional split out --------
template <int SPLIT>
__global__ __launch_bounds__(256)
void ln_kernel(const float* __restrict__ X, const float* __restrict__ gam,
               const float* __restrict__ bet, float* __restrict__ Y,
               __nv_bfloat16* __restrict__ Yh, __nv_bfloat16* __restrict__ Yl) {
    const int row = blockIdx.x;
    const int tid = threadIdx.x;
    const float4 v = ((const float4*)(X + (size_t)row * Hn))[tid];
    float s  = v.x + v.y + v.z + v.w;
    float ss = v.x * v.x + v.y * v.y + v.z * v.z + v.w * v.w;
#pragma unroll
    for (int o = 16; o > 0; o >>= 1) {
        s  += __shfl_xor_sync(0xffffffffu, s, o);
        ss += __shfl_xor_sync(0xffffffffu, ss, o);
    }
    __shared__ float sh_s[8], sh_ss[8];
    const int wid = tid >> 5, lane = tid & 31;
    if (lane == 0) { sh_s[wid] = s; sh_ss[wid] = ss; }
    __syncthreads();
    s = 0.f; ss = 0.f;
#pragma unroll
    for (int i = 0; i < 8; i++) { s += sh_s[i]; ss += sh_ss[i]; }
    const float mean = s * (1.0f / Hn);
    const float var  = ss * (1.0f / Hn) - mean * mean;
    const float rstd = rsqrtf(var + 1e-5f);
    const float4 gv = ((const float4*)gam)[tid];
    const float4 bv = ((const float4*)bet)[tid];
    float4 out;
    out.x = (v.x - mean) * rstd * gv.x + bv.x;
    out.y = (v.y - mean) * rstd * gv.y + bv.y;
    out.z = (v.z - mean) * rstd * gv.z + bv.z;
    out.w = (v.w - mean) * rstd * gv.w + bv.w;
    ((float4*)(Y + (size_t)row * Hn))[tid] = out;
    if (SPLIT) {
        __nv_bfloat16 h0 = __float2bfloat16(out.x), h1 = __float2bfloat16(out.y);
        __nv_bfloat16 h2 = __float2bfloat16(out.z), h3 = __float2bfloat16(out.w);
        size_t base2 = (size_t)row * (Hn / 2) + tid * 2;
        ((__nv_bfloat162*)Yh)[base2]     = __nv_bfloat162(h0, h1);
        ((__nv_bfloat162*)Yh)[base2 + 1] = __nv_bfloat162(h2, h3);
        ((__nv_bfloat162*)Yl)[base2] =
            __nv_bfloat162(__float2bfloat16(out.x - __bfloat162float(h0)),
                           __float2bfloat16(out.y - __bfloat162float(h1)));
        ((__nv_bfloat162*)Yl)[base2 + 1] =
            __nv_bfloat162(__float2bfloat16(out.z - __bfloat162float(h2)),
                           __float2bfloat16(out.w - __bfloat162float(h3)));
    }
}

// ---------------- launch ----------------------------------------------------
static float* symaddrf(const void* sym) {
    void* p = nullptr;
    cudaGetSymbolAddress(&p, sym);
    return (float*)p;
}
static __nv_bfloat16* symaddrb(const void* sym) {
    void* p = nullptr;
    cudaGetSymbolAddress(&p, sym);
    return (__nv_bfloat16*)p;
}

extern "C" void kernel_launch(void* const* d_in, const int* in_sizes, int n_in,
                              void* d_out, int out_size) {
    const float* hidden = (const float*)d_in[0];
    const float* mask   = (const float*)d_in[1];
    const float* Wq = (const float*)d_in[2];  const float* bq = (const float*)d_in[3];
    const float* Wk = (const float*)d_in[4];  const float* bk = (const float*)d_in[5];
    const float* Wv = (const float*)d_in[6];  const float* bv = (const float*)d_in[7];
    const float* Wao= (const float*)d_in[8];  const float* bao= (const float*)d_in[9];
    const float* g1 = (const float*)d_in[10]; const float* b1 = (const float*)d_in[11];
    const float* Wi = (const float*)d_in[12]; const float* bi = (const float*)d_in[13];
    const float* Wo = (const float*)d_in[14]; const float* bo = (const float*)d_in[15];
    const float* g2 = (const float*)d_in[16]; const float* b2 = (const float*)d_in[17];
    float* outp = (float*)d_out;

    float* y  = symaddrf(g_y);
    float* x1 = symaddrf(g_x1);
    float* x2 = symaddrf(g_x2);
    float* bqkv = symaddrf(g_bqkv);
    __nv_bfloat16* xh  = symaddrb(g_xh);  __nv_bfloat16* xl  = symaddrb(g_xl);
    __nv_bfloat16* qkvh = symaddrb(g_qkvh); __nv_bfloat16* qkvl = symaddrb(g_qkvl);
    __nv_bfloat16* cxh = symaddrb(g_cxh); __nv_bfloat16* cxl = symaddrb(g_cxl);
    __nv_bfloat16* fh  = symaddrb(g_fh);  __nv_bfloat16* fl  = symaddrb(g_fl);
    __nv_bfloat16* wth = symaddrb(g_wth); __nv_bfloat16* wtl = symaddrb(g_wtl);

    cudaFuncSetAttribute(flashmma_kernel, cudaFuncAttributeMaxDynamicSharedMemorySize, FSMEM);
    cudaFuncSetAttribute(bgemm_kernel<4>,  cudaFuncAttributeMaxDynamicSharedMemorySize, GSMEM);
    cudaFuncSetAttribute(bgemm_kernel<2>,  cudaFuncAttributeMaxDynamicSharedMemorySize, GSMEM);
    cudaFuncSetAttribute(bgemm_kernel<5>,  cudaFuncAttributeMaxDynamicSharedMemorySize, GSMEM);

    // ---- fused weight prep: ONE launch for all 12 matrices ----
    const int n4_hh = Hn * Hn / 4;
    const int n4_hf = Hn * FFn / 4;
    WSegTable T;
    {
        int c = 0, s = 0;
        for (int l = 0; l < Lnum; ++l) {
            const long long wb = (long long)l * LW_ELEMS;
            T.src[s] = Wq + (size_t)l*Hn*Hn; T.N[s] = Hn;  T.LD[s] = QKVW; T.OFF[s] = 0;
            T.dst[s] = wb + LW_QKV; T.cum[s] = c; c += n4_hh; s++;
            T.src[s] = Wk + (size_t)l*Hn*Hn; T.N[s] = Hn;  T.LD[s] = QKVW; T.OFF[s] = Hn;
            T.dst[s] = wb + LW_QKV; T.cum[s] = c; c += n4_hh; s++;
            T.src[s] = Wv + (size_t)l*Hn*Hn; T.N[s] = Hn;  T.LD[s] = QKVW; T.OFF[s] = 2*Hn;
            T.dst[s] = wb + LW_QKV; T.cum[s] = c; c += n4_hh; s++;
            T.src[s] = Wao+ (size_t)l*Hn*Hn; T.N[s] = Hn;  T.LD[s] = Hn;   T.OFF[s] = 0;
            T.dst[s] = wb + LW_AO;  T.cum[s] = c; c += n4_hh; s++;
            T.src[s] = Wi + (size_t)l*Hn*FFn; T.N[s] = FFn; T.LD[s] = FFn; T.OFF[s] = 0;
            T.dst[s] = wb + LW_I;   T.cum[s] = c; c += n4_hf; s++;
            T.src[s] = Wo + (size_t)l*FFn*Hn; T.N[s] = Hn;  T.LD[s] = Hn;  T.OFF[s] = 0;
            T.dst[s] = wb + LW_O;   T.cum[s] = c; c += n4_hf; s++;
        }
        T.cum[NSEG] = c;
    }
    wsplit_all_kernel<<<1184, 256>>>(T, wth, wtl);
    bconcat_kernel<<<(Lnum * QKVW + 255) / 256, 256>>>(bq, bk, bv, bqkv);
    split_kernel<<<Mrows * Hn / 1024, 256>>>(hidden, xh, xl, Mrows * Hn / 4);

    const dim3 gQKV(QKVW / 128, Mrows / 128);  // (24, 32)
    const dim3 gAO (Hn / 128,  Mrows / 128);   // (8, 32)
    const dim3 gFF1(FFn / 128, Mrows / 128);   // (32, 32)
    const dim3 gFA(Sn / 128, NHn, Bn);         // (16, 16, 2)

    for (int l = 0; l < Lnum; ++l) {
        const float* xf = (l == 0) ? hidden : x2;
        const size_t wb  = (size_t)l * LW_ELEMS;
        const size_t bo1 = (size_t)l * Hn;
        const size_t bio = (size_t)l * FFn;

        bgemm_kernel<4><<<gQKV, 256, GSMEM>>>(xh, xl, wth + wb + LW_QKV, wtl + wb + LW_QKV,
                                              bqkv + (size_t)l*QKVW, nullptr, nullptr,
                                              qkvh, qkvl, Hn, QKVW);

        flashmma_kernel<<<gFA, 256, FSMEM>>>(qkvh, qkvl, mask, cxh, cxl);

        bgemm_kernel<2><<<gAO, 256, GSMEM>>>(cxh, cxl, wth + wb + LW_AO, wtl + wb + LW_AO,
                                             bao + bo1, xf, y, nullptr, nullptr, Hn, Hn);
        ln_kernel<1><<<Mrows, 256>>>(y, g1 + bo1, b1 + bo1, x1, xh, xl);

        bgemm_kernel<5><<<gFF1, 256, GSMEM>>>(xh, xl, wth + wb + LW_I, wtl + wb + LW_I,
                                              bi + bio, nullptr, nullptr, fh, fl, Hn, FFn);
        bgemm_kernel<2><<<gAO, 256, GSMEM>>>(fh, fl, wth + wb + LW_O, wtl + wb + LW_O,
                                             bo + bo1, x1, y, nullptr, nullptr, FFn, Hn);
        if (l == Lnum - 1)
            ln_kernel<0><<<Mrows, 256>>>(y, g2 + bo1, b2 + bo1, outp, nullptr, nullptr);
        else
            ln_kernel<1><<<Mrows, 256>>>(y, g2 + bo1, b2 + bo1, x2, xh, xl);
    }
}

// round 16
// speedup vs baseline: 1.0765x; 1.0059x over previous
#include <cuda_runtime.h>
#include <cuda_bf16.h>
#include <math.h>
#include <stdint.h>

// Problem constants
#define Lnum 2
#define Bn   2
#define Sn   2048
#define Hn   1024
#define NHn  16
#define DHn  64
#define FFn  4096
#define Mrows (Bn*Sn)   // 4096
#define QKVW 3072

#define LOG2E 1.4426950408889634f

// ---------------- scratch (device globals; no allocation allowed) ----------
__device__ float g_y  [Mrows*Hn];
__device__ float g_x1 [Mrows*Hn];
__device__ float g_x2 [Mrows*Hn];
__device__ float g_bqkv[Lnum*QKVW];

__device__ __nv_bfloat16 g_xh[Mrows*Hn],  g_xl[Mrows*Hn];
__device__ __nv_bfloat16 g_qkvh[(size_t)Mrows*QKVW], g_qkvl[(size_t)Mrows*QKVW];
__device__ __nv_bfloat16 g_cxh[Mrows*Hn], g_cxl[Mrows*Hn];
__device__ __nv_bfloat16 g_fh[(size_t)Mrows*FFn], g_fl[(size_t)Mrows*FFn];

// K-major split weights per layer: [QKV fused 1024x3072 | AO 1024x1024 | WI 1024x4096 | WO 4096x1024]
#define LW_QKV 0
#define LW_AO  3145728
#define LW_I   4194304
#define LW_O   8388608
#define LW_ELEMS 12582912
__device__ __nv_bfloat16 g_wth[(size_t)Lnum*LW_ELEMS];
__device__ __nv_bfloat16 g_wtl[(size_t)Lnum*LW_ELEMS];

// ---------------- PTX helpers (sm_80-era ISA only) ---------------------------
__device__ __forceinline__ uint32_t smem_u32(const void* p) {
    uint32_t a;
    asm("{ .reg .u64 t; cvta.to.shared.u64 t, %1; cvt.u32.u64 %0, t; }" : "=r"(a) : "l"(p));
    return a;
}
__device__ __forceinline__ void ldmx4(uint32_t* r, uint32_t addr) {
    asm volatile("ldmatrix.sync.aligned.m8n8.x4.shared.b16 {%0,%1,%2,%3}, [%4];"
                 : "=r"(r[0]), "=r"(r[1]), "=r"(r[2]), "=r"(r[3]) : "r"(addr));
}
__device__ __forceinline__ void ldmx4t(uint32_t* r, uint32_t addr) {
    asm volatile("ldmatrix.sync.aligned.m8n8.x4.trans.shared.b16 {%0,%1,%2,%3}, [%4];"
                 : "=r"(r[0]), "=r"(r[1]), "=r"(r[2]), "=r"(r[3]) : "r"(addr));
}
__device__ __forceinline__ void mma_bf16(float* c, const uint32_t* a, const uint32_t* b) {
    asm volatile(
        "mma.sync.aligned.m16n8k16.row.col.f32.bf16.bf16.f32 "
        "{%0,%1,%2,%3}, {%4,%5,%6,%7}, {%8,%9}, {%0,%1,%2,%3};"
        : "+f"(c[0]), "+f"(c[1]), "+f"(c[2]), "+f"(c[3])
        : "r"(a[0]), "r"(a[1]), "r"(a[2]), "r"(a[3]), "r"(b[0]), "r"(b[1]));
}
#define CP_COMMIT() asm volatile("cp.async.commit_group;" ::: "memory")
#define CP_WAIT(N)  asm volatile("cp.async.wait_group %0;" :: "n"(N) : "memory")
#define CP16(so, g) asm volatile("cp.async.ca.shared.global [%0], [%1], 16;" :: "r"(so), "l"(g))

// ---------------- conversion kernels ----------------------------------------
__global__ __launch_bounds__(256)
void split_kernel(const float* __restrict__ x, __nv_bfloat16* __restrict__ h,
                  __nv_bfloat16* __restrict__ l, int n4) {
    int i = blockIdx.x * 256 + threadIdx.x;
    if (i >= n4) return;
    float4 v = ((const float4*)x)[i];
    __nv_bfloat16 h0 = __float2bfloat16(v.x);
    __nv_bfloat16 h1 = __float2bfloat16(v.y);
    __nv_bfloat16 h2 = __float2bfloat16(v.z);
    __nv_bfloat16 h3 = __float2bfloat16(v.w);
    ((__nv_bfloat162*)h)[2*i]   = __nv_bfloat162(h0, h1);
    ((__nv_bfloat162*)h)[2*i+1] = __nv_bfloat162(h2, h3);
    ((__nv_bfloat162*)l)[2*i]   = __nv_bfloat162(__float2bfloat16(v.x - __bfloat162float(h0)),
                                                 __float2bfloat16(v.y - __bfloat162float(h1)));
    ((__nv_bfloat162*)l)[2*i+1] = __nv_bfloat162(__float2bfloat16(v.z - __bfloat162float(h2)),
                                                 __float2bfloat16(v.w - __bfloat162float(h3)));
}

// bias concat for BOTH layers
__global__ __launch_bounds__(256)
void bconcat_kernel(const float* __restrict__ bq, const float* __restrict__ bk,
                    const float* __restrict__ bv, float* __restrict__ out) {
    int i = blockIdx.x * 256 + threadIdx.x;
    if (i >= Lnum * QKVW) return;
    int l = i / QKVW, j = i - l * QKVW;
    float v = (j < Hn) ? bq[l * Hn + j]
             : ((j < 2 * Hn) ? bk[l * Hn + j - Hn] : bv[l * Hn + j - 2 * Hn]);
    out[i] = v;
}

// Fused weight split: ALL 12 weight matrices in one launch.
#define NSEG 12
struct WSegTable {
    const float* src[NSEG];
    int N[NSEG], LD[NSEG], OFF[NSEG];
    long long dst[NSEG];
    int cum[NSEG + 1];
};

__global__ __launch_bounds__(256)
void wsplit_all_kernel(WSegTable T, __nv_bfloat16* __restrict__ th,
                       __nv_bfloat16* __restrict__ tl) {
    const int total = T.cum[NSEG];
    for (int i = blockIdx.x * 256 + threadIdx.x; i < total; i += gridDim.x * 256) {
        int s = 0;
#pragma unroll
        for (int j = 1; j < NSEG; j++) s += (i >= T.cum[j]);
        const int i4 = i - T.cum[s];
        const int idx = i4 * 4;
        const int N = T.N[s];
        const int k = idx / N, n = idx - k * N;
        float4 v = *(const float4*)(T.src[s] + idx);
        const size_t o = (size_t)T.dst[s] + (size_t)k * T.LD[s] + T.OFF[s] + n;
        __nv_bfloat16 h0 = __float2bfloat16(v.x);
        __nv_bfloat16 h1 = __float2bfloat16(v.y);
        __nv_bfloat16 h2 = __float2bfloat16(v.z);
        __nv_bfloat16 h3 = __float2bfloat16(v.w);
        *(__nv_bfloat162*)(th + o)     = __nv_bfloat162(h0, h1);
        *(__nv_bfloat162*)(th + o + 2) = __nv_bfloat162(h2, h3);
        *(__nv_bfloat162*)(tl + o) =
            __nv_bfloat162(__float2bfloat16(v.x - __bfloat162float(h0)),
                           __float2bfloat16(v.y - __bfloat162float(h1)));
        *(__nv_bfloat162*)(tl + o + 2) =
            __nv_bfloat162(__float2bfloat16(v.z - __bfloat162float(h2)),
                           __float2bfloat16(v.w - __bfloat162float(h3)));
    }
}

// ---------------- bf16-split GEMM via mma.sync (HMMA) -----------------------
// R11 config + A-fragment software pipelining.
// 128x128 CTA, 256 threads (8 warps = 2M x 4N, warp tile 64x32), BK=32,
// 2-stage cp.async (.ca), 2 CTAs/SM.
// MODE bits: 1=gelu, 2=resid, 4=split-out (bf16 hi/lo)
#define BKc 32
#define ROWB 80
#define ROWB_B 272
#define MATB_A (128*ROWB)            // 10240
#define MATB_B (32*ROWB_B)           // 8704
#define STAGEB (2*MATB_A + 2*MATB_B) // 37888
#define GSMEM (2*STAGEB)             // 75776

__device__ __forceinline__ float gelu_exact(float x) {
    return 0.5f * x * (1.0f + erff(x * 0.7071067811865475f));
}

// A tile 128x32 bf16 = 512 16B chunks; 2 iters
__device__ __forceinline__ void cp_tile_a(uint32_t sdst, const __nv_bfloat16* __restrict__ src,
                                          int row0, int K, int k0, int tid) {
#pragma unroll
    for (int j = 0; j < 2; j++) {
        int e = tid + j * 256;
        int r = e >> 2, c = e & 3;
        uint32_t so = sdst + (uint32_t)(r * ROWB + c * 16);
        const void* g = src + (size_t)(row0 + r) * K + k0 + c * 8;
        CP16(so, g);
    }
}
// B tile 32x128 bf16 (K-major rows of 256B) = 512 16B chunks; 2 iters
__device__ __forceinline__ void cp_tile_b(uint32_t sdst, const __nv_bfloat16* __restrict__ src,
                                          int n0, int N, int k0, int tid) {
#pragma unroll
    for (int j = 0; j < 2; j++) {
        int e = tid + j * 256;
        int r = e >> 4, c = e & 15;
        uint32_t so = sdst + (uint32_t)(r * ROWB_B + c * 16);
        const void* g = src + (size_t)(k0 + r) * N + n0 + c * 8;
        CP16(so, g);
    }
}

template <int MODE>
__global__ __launch_bounds__(256, 2)
void bgemm_kernel(const __nv_bfloat16* __restrict__ Ah, const __nv_bfloat16* __restrict__ Al,
                  const __nv_bfloat16* __restrict__ Bh, const __nv_bfloat16* __restrict__ Bl,
                  const float* __restrict__ bias, const float* __restrict__ resid,
                  float* __restrict__ C, __nv_bfloat16* __restrict__ Ch,
                  __nv_bfloat16* __restrict__ Cl, int K, int N) {
    extern __shared__ char smem_raw[];
    const uint32_t sb = smem_u32(smem_raw);

    const int tid = threadIdx.x;
    const int lane = tid & 31, wid = tid >> 5;
    const int wm = wid >> 2, wn = wid & 3;    // 2M x 4N warps; warp tile 64x32
    const int bx = blockIdx.x, by = blockIdx.y;
    const int arow0 = by * 128, bcol0 = bx * 128;

    float acc[4][4][4];
#pragma unroll
    for (int i = 0; i < 4; i++)
#pragma unroll
        for (int n = 0; n < 4; n++)
#pragma unroll
            for (int t = 0; t < 4; t++) acc[i][n][t] = 0.f;

    const uint32_t a_off = (uint32_t)((wm * 64 + (lane & 15)) * ROWB + ((lane & 16) ? 16 : 0));
    const uint32_t b_off = (uint32_t)((lane & 15) * ROWB_B + wn * 64 + ((lane & 16) ? 16 : 0));

    const int nk = K / BKc;

    {   // prologue: stage 0
        cp_tile_a(sb,                       Ah, arow0, K, 0, tid);
        cp_tile_a(sb + MATB_A,              Al, arow0, K, 0, tid);
        cp_tile_b(sb + 2 * MATB_A,          Bh, bcol0, N, 0, tid);
        cp_tile_b(sb + 2 * MATB_A + MATB_B, Bl, bcol0, N, 0, tid);
        CP_COMMIT();
    }

    for (int kc = 0; kc < nk; ++kc) {
        const int s = kc & 1;
        if (kc + 1 < nk) {
            uint32_t st = sb + (uint32_t)(((kc + 1) & 1) * STAGEB);
            const int k0 = (kc + 1) * BKc;
            cp_tile_a(st,                       Ah, arow0, K, k0, tid);
            cp_tile_a(st + MATB_A,              Al, arow0, K, k0, tid);
            cp_tile_b(st + 2 * MATB_A,          Bh, bcol0, N, k0, tid);
            cp_tile_b(st + 2 * MATB_A + MATB_B, Bl, bcol0, N, k0, tid);
            CP_COMMIT();
            CP_WAIT(1);
        } else {
            CP_WAIT(0);
        }
        __syncthreads();

        const uint32_t st = sb + (uint32_t)(s * STAGEB);
        const uint32_t aH = st + a_off;
        const uint32_t aL = st + MATB_A + a_off;
        const uint32_t bH = st + 2 * MATB_A + b_off;
        const uint32_t bL = st + 2 * MATB_A + MATB_B + b_off;

        // compute: 8 steps = 2 ks x 4 i, A-fragments double-buffered one ahead
        uint32_t ah[2][4], al[2][4];
        uint32_t bh[4][2], bl[4][2];
        ldmx4(ah[0], aH);          // step 0: i=0, ks=0 -> offset 0
        ldmx4(al[0], aL);
#pragma unroll
        for (int step = 0; step < 8; ++step) {
            const int ks = step >> 2;
            const int cur = step & 1;
            if ((step & 3) == 0) {   // new ks: load B fragments
                const uint32_t ksoB = (uint32_t)(ks * 16 * ROWB_B);
#pragma unroll
                for (int j = 0; j < 2; j++) {
                    uint32_t r[4];
                    ldmx4t(r, bH + ksoB + (uint32_t)(j * 32));
                    bh[2*j][0] = r[0]; bh[2*j][1] = r[1];
                    bh[2*j+1][0] = r[2]; bh[2*j+1][1] = r[3];
                    ldmx4t(r, bL + ksoB + (uint32_t)(j * 32));
                    bl[2*j][0] = r[0]; bl[2*j][1] = r[1];
                    bl[2*j+1][0] = r[2]; bl[2*j+1][1] = r[3];
                }
            }
            if (step < 7) {          // prefetch next step's A fragments
                const int ns = step + 1;
                const uint32_t ao = (uint32_t)((ns & 3) * 16 * ROWB + (ns >> 2) * 32);
                ldmx4(ah[cur ^ 1], aH + ao);
                ldmx4(al[cur ^ 1], aL + ao);
            }
            const int i = step & 3;
#pragma unroll
            for (int n = 0; n < 4; n++) mma_bf16(acc[i][n], ah[cur], bh[n]);
#pragma unroll
            for (int n = 0; n < 4; n++) mma_bf16(acc[i][n], ah[cur], bl[n]);
#pragma unroll
            for (int n = 0; n < 4; n++) mma_bf16(acc[i][n], al[cur], bh[n]);
        }
        __syncthreads();
    }

    const int gid = lane >> 2, tig = lane & 3;
    float bsv0[4], bsv1[4];
#pragma unroll
    for (int n = 0; n < 4; n++) {
        const int cg = bx * 128 + wn * 32 + n * 8 + tig * 2;
        bsv0[n] = bias[cg];
        bsv1[n] = bias[cg + 1];
    }
#pragma unroll
    for (int i = 0; i < 4; i++) {
        const int r0 = by * 128 + wm * 64 + i * 16 + gid;
#pragma unroll
        for (int n = 0; n < 4; n++) {
            const int cg = bx * 128 + wn * 32 + n * 8 + tig * 2;
            float v0 = acc[i][n][0] + bsv0[n];
            float v1 = acc[i][n][1] + bsv1[n];
            float v2 = acc[i][n][2] + bsv0[n];
            float v3 = acc[i][n][3] + bsv1[n];
            if (MODE & 1) {
                v0 = gelu_exact(v0); v1 = gelu_exact(v1);
                v2 = gelu_exact(v2); v3 = gelu_exact(v3);
            }
            if (MODE & 2) {
                const float* R0 = resid + (size_t)r0 * N + cg;
                const float* R1 = resid + (size_t)(r0 + 8) * N + cg;
                v0 += R0[0]; v1 += R0[1]; v2 += R1[0]; v3 += R1[1];
            }
            if (MODE & 4) {
                __nv_bfloat16 h0 = __float2bfloat16(v0), h1 = __float2bfloat16(v1);
                __nv_bfloat16 h2 = __float2bfloat16(v2), h3 = __float2bfloat16(v3);
                *(__nv_bfloat162*)(Ch + (size_t)r0 * N + cg)       = __nv_bfloat162(h0, h1);
                *(__nv_bfloat162*)(Ch + (size_t)(r0 + 8) * N + cg) = __nv_bfloat162(h2, h3);
                *(__nv_bfloat162*)(Cl + (size_t)r0 * N + cg) =
                    __nv_bfloat162(__float2bfloat16(v0 - __bfloat162float(h0)),
                                   __float2bfloat16(v1 - __bfloat162float(h1)));
                *(__nv_bfloat162*)(Cl + (size_t)(r0 + 8) * N + cg) =
                    __nv_bfloat162(__float2bfloat16(v2 - __bfloat162float(h2)),
                                   __float2bfloat16(v3 - __bfloat162float(h3)));
            } else {
                *(float2*)(C + (size_t)r0 * N + cg)       = make_float2(v0, v1);
                *(float2*)(C + (size_t)(r0 + 8) * N + cg) = make_float2(v2, v3);
            }
        }
    }
}

// ---------------- Flash attention via mma.sync (bf16 split) -----------------
#define FQH 0
#define FQL 16384
#define FKV0 32768
#define FMSK 98304
#define FSMEM 98816
#define SCL (0.125f * LOG2E)

__device__ __forceinline__ void fa_cp_kv(uint32_t sbase, const __nv_bfloat16* __restrict__ src,
                                         size_t gbase, int krow0, int tid) {
#pragma unroll
    for (int j = 0; j < 2; j++) {
        int e = tid + j * 256;
        int r = e >> 3, c = e & 7;
        uint32_t so = sbase + (uint32_t)(r * 128 + ((c ^ (r & 7)) * 16));
        const void* g = src + gbase + (size_t)(krow0 + r) * QKVW + c * 8;
        CP16(so, g);
    }
}

__global__ __launch_bounds__(256, 2)
void flashmma_kernel(const __nv_bfloat16* __restrict__ QKVh,
                     const __nv_bfloat16* __restrict__ QKVl,
                     const float* __restrict__ mask,
                     __nv_bfloat16* __restrict__ Ch, __nv_bfloat16* __restrict__ Cl) {
    extern __shared__ char sm[];
    const uint32_t sb = smem_u32(sm);
    const int tid = threadIdx.x, l = tid & 31, w = tid >> 5;
    const int gid = l >> 2, tig = l & 3;
    const int qt = blockIdx.x, h = blockIdx.y, b = blockIdx.z;
    const size_t gq = (size_t)b * Sn * QKVW + (size_t)h * DHn;
    const size_t gk = gq + Hn;
    const size_t gv = gq + 2 * Hn;
    const int qrow0 = qt * 128;

#pragma unroll
    for (int j = 0; j < 4; j++) {
        int e = tid + j * 256;
        int r = e >> 3, c = e & 7;
        uint32_t sw = (uint32_t)(r * 128 + ((c ^ (r & 7)) * 16));
        size_t g = gq + (size_t)(qrow0 + r) * QKVW + c * 8;
        CP16(sb + FQH + sw, QKVh + g);
        CP16(sb + FQL + sw, QKVl + g);
    }
    {
        uint32_t st = sb + FKV0;
        fa_cp_kv(st,         QKVh, gk, 0, tid);
        fa_cp_kv(st + 8192,  QKVl, gk, 0, tid);
        fa_cp_kv(st + 16384, QKVh, gv, 0, tid);
        fa_cp_kv(st + 24576, QKVl, gv, 0, tid);
        if (tid < 16) CP16(sb + FMSK + tid * 16, mask + b * Sn + tid * 4);
    }
    CP_COMMIT();

    float m0 = -1e30f, m1 = -1e30f, li0 = 0.f, li1 = 0.f;
    float o[8][4];
#pragma unroll
    for (int j = 0; j < 8; j++)
#pragma unroll
        for (int t = 0; t < 4; t++) o[j][t] = 0.f;

    const int rowq = w * 16 + (l & 15);
    const uint32_t qbaseH = sb + FQH + (uint32_t)(rowq * 128);
    const int rq7 = rowq & 7;
    const int qsel = l >> 4;

    for (int kt = 0; kt < Sn / 64; ++kt) {
        const int s = kt & 1;
        if (kt + 1 < Sn / 64) {
            uint32_t st = sb + FKV0 + (uint32_t)((s ^ 1) * 32768);
            fa_cp_kv(st,         QKVh, gk, (kt + 1) * 64, tid);
            fa_cp_kv(st + 8192,  QKVl, gk, (kt + 1) * 64, tid);
            fa_cp_kv(st + 16384, QKVh, gv, (kt + 1) * 64, tid);
            fa_cp_kv(st + 24576, QKVl, gv, (kt + 1) * 64, tid);
            if (tid < 16)
                CP16(sb + FMSK + (uint32_t)((s ^ 1) * 256 + tid * 16),
                     mask + b * Sn + (kt + 1) * 64 + tid * 4);
            CP_COMMIT();
            CP_WAIT(1);
        } else {
            CP_WAIT(0);
        }
        __syncthreads();

        const uint32_t stK = sb + FKV0 + (uint32_t)(s * 32768);

        float sc[8][4];
#pragma unroll
        for (int j = 0; j < 8; j++)
#pragma unroll
            for (int t = 0; t < 4; t++) sc[j][t] = 0.f;

#pragma unroll
        for (int kc = 0; kc < 4; ++kc) {
            uint32_t aH[4], aL[4];
            uint32_t qa = qbaseH + (uint32_t)((((2 * kc + qsel)) ^ rq7) * 16);
            ldmx4(aH, qa);
            ldmx4(aL, qa + 16384);
#pragma unroll
            for (int j = 0; j < 4; ++j) {
                int rowk = j * 16 + (l & 7) + ((l & 16) >> 1);
                uint32_t ka = stK + (uint32_t)(rowk * 128 +
                              (((2 * kc + ((l & 8) >> 3)) ^ (rowk & 7)) * 16));
                uint32_t bH[4], bL[4];
                ldmx4(bH, ka);
                ldmx4(bL, ka + 8192);
                mma_bf16(sc[2*j],   aH, bH);
                mma_bf16(sc[2*j+1], aH, bH + 2);
                mma_bf16(sc[2*j],   aH, bL);
                mma_bf16(sc[2*j+1], aH, bL + 2);
                mma_bf16(sc[2*j],   aL, bH);
                mma_bf16(sc[2*j+1], aL, bH + 2);
            }
        }

        const float* mk = (const float*)(sm + FMSK + s * 256);
        float tmax0 = -1e30f, tmax1 = -1e30f;
#pragma unroll
        for (int j = 0; j < 8; ++j) {
            float mL0 = mk[j * 8 + 2 * tig] * LOG2E;
            float mL1 = mk[j * 8 + 2 * tig + 1] * LOG2E;
            sc[j][0] = fmaf(sc[j][0], SCL, mL0);
            sc[j][1] = fmaf(sc[j][1], SCL, mL1);
            sc[j][2] = fmaf(sc[j][2], SCL, mL0);
            sc[j][3] = fmaf(sc[j][3], SCL, mL1);
            tmax0 = fmaxf(tmax0, fmaxf(sc[j][0], sc[j][1]));
            tmax1 = fmaxf(tmax1, fmaxf(sc[j][2], sc[j][3]));
        }
        tmax0 = fmaxf(tmax0, __shfl_xor_sync(0xffffffffu, tmax0, 1));
        tmax0 = fmaxf(tmax0, __shfl_xor_sync(0xffffffffu, tmax0, 2));
        tmax1 = fmaxf(tmax1, __shfl_xor_sync(0xffffffffu, tmax1, 1));
        tmax1 = fmaxf(tmax1, __shfl_xor_sync(0xffffffffu, tmax1, 2));
        float mn0 = fmaxf(m0, tmax0), mn1 = fmaxf(m1, tmax1);
        float a0 = exp2f(m0 - mn0), a1 = exp2f(m1 - mn1);
        m0 = mn0; m1 = mn1;
        float rs0 = 0.f, rs1 = 0.f;
#pragma unroll
        for (int j = 0; j < 8; ++j) {
            sc[j][0] = exp2f(sc[j][0] - mn0);
            sc[j][1] = exp2f(sc[j][1] - mn0);
            sc[j][2] = exp2f(sc[j][2] - mn1);
            sc[j][3] = exp2f(sc[j][3] - mn1);
            rs0 += sc[j][0] + sc[j][1];
            rs1 += sc[j][2] + sc[j][3];
        }
        rs0 += __shfl_xor_sync(0xffffffffu, rs0, 1);
        rs0 += __shfl_xor_sync(0xffffffffu, rs0, 2);
        rs1 += __shfl_xor_sync(0xffffffffu, rs1, 1);
        rs1 += __shfl_xor_sync(0xffffffffu, rs1, 2);
        li0 = li0 * a0 + rs0;
        li1 = li1 * a1 + rs1;
#pragma unroll
        for (int j = 0; j < 8; ++j) {
            o[j][0] *= a0; o[j][1] *= a0; o[j][2] *= a1; o[j][3] *= a1;
        }

        const uint32_t stV = stK + 16384;
#pragma unroll
        for (int kc = 0; kc < 4; ++kc) {
            uint32_t paH[4], paL[4];
#pragma unroll
            for (int q2 = 0; q2 < 2; ++q2) {
                const float* pp = sc[2 * kc + q2];
                __nv_bfloat16 h0 = __float2bfloat16(pp[0]);
                __nv_bfloat16 h1 = __float2bfloat16(pp[1]);
                __nv_bfloat16 h2 = __float2bfloat16(pp[2]);
                __nv_bfloat16 h3 = __float2bfloat16(pp[3]);
                __nv_bfloat162 ph01(h0, h1), ph23(h2, h3);
                paH[2 * q2]     = *(uint32_t*)&ph01;
                paH[2 * q2 + 1] = *(uint32_t*)&ph23;
                __nv_bfloat162 pl01(__float2bfloat16(pp[0] - __bfloat162float(h0)),
                                    __float2bfloat16(pp[1] - __bfloat162float(h1)));
                __nv_bfloat162 pl23(__float2bfloat16(pp[2] - __bfloat162float(h2)),
                                    __float2bfloat16(pp[3] - __bfloat162float(h3)));
                paL[2 * q2]     = *(uint32_t*)&pl01;
                paL[2 * q2 + 1] = *(uint32_t*)&pl23;
            }
#pragma unroll
            for (int jd = 0; jd < 4; ++jd) {
                int rowv = kc * 16 + (l & 15);
                uint32_t va = stV + (uint32_t)(rowv * 128 +
                              (((2 * jd + (l >> 4)) ^ (rowv & 7)) * 16));
                uint32_t bvH[4], bvL[4];
                ldmx4t(bvH, va);
                ldmx4t(bvL, va + 8192);
                mma_bf16(o[2*jd],   paH, bvH);
                mma_bf16(o[2*jd+1], paH, bvH + 2);
                mma_bf16(o[2*jd],   paH, bvL);
                mma_bf16(o[2*jd+1], paH, bvL + 2);
                mma_bf16(o[2*jd],   paL, bvH);
                mma_bf16(o[2*jd+1], paL, bvH + 2);
            }
        }
        __syncthreads();
    }

    const float i0 = 1.f / li0, i1 = 1.f / li1;
    const size_t gctx = (size_t)b * Sn * Hn + (size_t)h * DHn;
    const size_t r0o = gctx + (size_t)(qrow0 + w * 16 + gid) * Hn;
    const size_t r1o = r0o + (size_t)8 * Hn;
#pragma unroll
    for (int j = 0; j < 8; ++j) {
        int col = j * 8 + 2 * tig;
        float v0 = o[j][0] * i0, v1 = o[j][1] * i0;
        float v2 = o[j][2] * i1, v3 = o[j][3] * i1;
        __nv_bfloat16 h0 = __float2bfloat16(v0), h1 = __float2bfloat16(v1);
        __nv_bfloat16 h2 = __float2bfloat16(v2), h3 = __float2bfloat16(v3);
        *(__nv_bfloat162*)(Ch + r0o + col) = __nv_bfloat162(h0, h1);
        *(__nv_bfloat162*)(Ch + r1o + col) = __nv_bfloat162(h2, h3);
        *(__nv_bfloat162*)(Cl + r0o + col) =
            __nv_bfloat162(__float2bfloat16(v0 - __bfloat162float(h0)),
                           __float2bfloat16(v1 - __bfloat162float(h1)));
        *(__nv_bfloat162*)(Cl + r1o + col) =
            __nv_bfloat162(__float2bfloat16(v2 - __bfloat162float(h2)),
                           __float2bfloat16(v3 - __bfloat162float(h3)));
    }
}

// ---------------- LayerNorm over last dim (1024), optional split out --------
template <int SPLIT>
__global__ __launch_bounds__(256)
void ln_kernel(const float* __restrict__ X, const float* __restrict__ gam,
               const float* __restrict__ bet, float* __restrict__ Y,
               __nv_bfloat16* __restrict__ Yh, __nv_bfloat16* __restrict__ Yl) {
    const int row = blockIdx.x;
    const int tid = threadIdx.x;
    const float4 v = ((const float4*)(X + (size_t)row * Hn))[tid];
    float s  = v.x + v.y + v.z + v.w;
    float ss = v.x * v.x + v.y * v.y + v.z * v.z + v.w * v.w;
#pragma unroll
    for (int o = 16; o > 0; o >>= 1) {
        s  += __shfl_xor_sync(0xffffffffu, s, o);
        ss += __shfl_xor_sync(0xffffffffu, ss, o);
    }
    __shared__ float sh_s[8], sh_ss[8];
    const int wid = tid >> 5, lane = tid & 31;
    if (lane == 0) { sh_s[wid] = s; sh_ss[wid] = ss; }
    __syncthreads();
    s = 0.f; ss = 0.f;
#pragma unroll
    for (int i = 0; i < 8; i++) { s += sh_s[i]; ss += sh_ss[i]; }
    const float mean = s * (1.0f / Hn);
    const float var  = ss * (1.0f / Hn) - mean * mean;
    const float rstd = rsqrtf(var + 1e-5f);
    const float4 gv = ((const float4*)gam)[tid];
    const float4 bv = ((const float4*)bet)[tid];
    float4 out;
    out.x = (v.x - mean) * rstd * gv.x + bv.x;
    out.y = (v.y - mean) * rstd * gv.y + bv.y;
    out.z = (v.z - mean) * rstd * gv.z + bv.z;
    out.w = (v.w - mean) * rstd * gv.w + bv.w;
    ((float4*)(Y + (size_t)row * Hn))[tid] = out;
    if (SPLIT) {
        __nv_bfloat16 h0 = __float2bfloat16(out.x), h1 = __float2bfloat16(out.y);
        __nv_bfloat16 h2 = __float2bfloat16(out.z), h3 = __float2bfloat16(out.w);
        size_t base2 = (size_t)row * (Hn / 2) + tid * 2;
        ((__nv_bfloat162*)Yh)[base2]     = __nv_bfloat162(h0, h1);
        ((__nv_bfloat162*)Yh)[base2 + 1] = __nv_bfloat162(h2, h3);
        ((__nv_bfloat162*)Yl)[base2] =
            __nv_bfloat162(__float2bfloat16(out.x - __bfloat162float(h0)),
                           __float2bfloat16(out.y - __bfloat162float(h1)));
        ((__nv_bfloat162*)Yl)[base2 + 1] =
            __nv_bfloat162(__float2bfloat16(out.z - __bfloat162float(h2)),
                           __float2bfloat16(out.w - __bfloat162float(h3)));
    }
}

// ---------------- launch ----------------------------------------------------
static float* symaddrf(const void* sym) {
    void* p = nullptr;
    cudaGetSymbolAddress(&p, sym);
    return (float*)p;
}
static __nv_bfloat16* symaddrb(const void* sym) {
    void* p = nullptr;
    cudaGetSymbolAddress(&p, sym);
    return (__nv_bfloat16*)p;
}

extern "C" void kernel_launch(void* const* d_in, const int* in_sizes, int n_in,
                              void* d_out, int out_size) {
    const float* hidden = (const float*)d_in[0];
    const float* mask   = (const float*)d_in[1];
    const float* Wq = (const float*)d_in[2];  const float* bq = (const float*)d_in[3];
    const float* Wk = (const float*)d_in[4];  const float* bk = (const float*)d_in[5];
    const float* Wv = (const float*)d_in[6];  const float* bv = (const float*)d_in[7];
    const float* Wao= (const float*)d_in[8];  const float* bao= (const float*)d_in[9];
    const float* g1 = (const float*)d_in[10]; const float* b1 = (const float*)d_in[11];
    const float* Wi = (const float*)d_in[12]; const float* bi = (const float*)d_in[13];
    const float* Wo = (const float*)d_in[14]; const float* bo = (const float*)d_in[15];
    const float* g2 = (const float*)d_in[16]; const float* b2 = (const float*)d_in[17];
    float* outp = (float*)d_out;

    float* y  = symaddrf(g_y);
    float* x1 = symaddrf(g_x1);
    float* x2 = symaddrf(g_x2);
    float* bqkv = symaddrf(g_bqkv);
    __nv_bfloat16* xh  = symaddrb(g_xh);  __nv_bfloat16* xl  = symaddrb(g_xl);
    __nv_bfloat16* qkvh = symaddrb(g_qkvh); __nv_bfloat16* qkvl = symaddrb(g_qkvl);
    __nv_bfloat16* cxh = symaddrb(g_cxh); __nv_bfloat16* cxl = symaddrb(g_cxl);
    __nv_bfloat16* fh  = symaddrb(g_fh);  __nv_bfloat16* fl  = symaddrb(g_fl);
    __nv_bfloat16* wth = symaddrb(g_wth); __nv_bfloat16* wtl = symaddrb(g_wtl);

    cudaFuncSetAttribute(flashmma_kernel, cudaFuncAttributeMaxDynamicSharedMemorySize, FSMEM);
    cudaFuncSetAttribute(bgemm_kernel<4>,  cudaFuncAttributeMaxDynamicSharedMemorySize, GSMEM);
    cudaFuncSetAttribute(bgemm_kernel<2>,  cudaFuncAttributeMaxDynamicSharedMemorySize, GSMEM);
    cudaFuncSetAttribute(bgemm_kernel<5>,  cudaFuncAttributeMaxDynamicSharedMemorySize, GSMEM);

    // ---- fused weight prep: ONE launch for all 12 matrices ----
    const int n4_hh = Hn * Hn / 4;
    const int n4_hf = Hn * FFn / 4;
    WSegTable T;
    {
        int c = 0, s = 0;
        for (int l = 0; l < Lnum; ++l) {
            const long long wb = (long long)l * LW_ELEMS;
            T.src[s] = Wq + (size_t)l*Hn*Hn; T.N[s] = Hn;  T.LD[s] = QKVW; T.OFF[s] = 0;
            T.dst[s] = wb + LW_QKV; T.cum[s] = c; c += n4_hh; s++;
            T.src[s] = Wk + (size_t)l*Hn*Hn; T.N[s] = Hn;  T.LD[s] = QKVW; T.OFF[s] = Hn;
            T.dst[s] = wb + LW_QKV; T.cum[s] = c; c += n4_hh; s++;
            T.src[s] = Wv + (size_t)l*Hn*Hn; T.N[s] = Hn;  T.LD[s] = QKVW; T.OFF[s] = 2*Hn;
            T.dst[s] = wb + LW_QKV; T.cum[s] = c; c += n4_hh; s++;
            T.src[s] = Wao+ (size_t)l*Hn*Hn; T.N[s] = Hn;  T.LD[s] = Hn;   T.OFF[s] = 0;
            T.dst[s] = wb + LW_AO;  T.cum[s] = c; c += n4_hh; s++;
            T.src[s] = Wi + (size_t)l*Hn*FFn; T.N[s] = FFn; T.LD[s] = FFn; T.OFF[s] = 0;
            T.dst[s] = wb + LW_I;   T.cum[s] = c; c += n4_hf; s++;
            T.src[s] = Wo + (size_t)l*FFn*Hn; T.N[s] = Hn;  T.LD[s] = Hn;  T.OFF[s] = 0;
            T.dst[s] = wb + LW_O;   T.cum[s] = c; c += n4_hf; s++;
        }
        T.cum[NSEG] = c;
    }
    wsplit_all_kernel<<<1184, 256>>>(T, wth, wtl);
    bconcat_kernel<<<(Lnum * QKVW + 255) / 256, 256>>>(bq, bk, bv, bqkv);
    split_kernel<<<Mrows * Hn / 1024, 256>>>(hidden, xh, xl, Mrows * Hn / 4);

    const dim3 gQKV(QKVW / 128, Mrows / 128);  // (24, 32)
    const dim3 gAO (Hn / 128,  Mrows / 128);   // (8, 32)
    const dim3 gFF1(FFn / 128, Mrows / 128);   // (32, 32)
    const dim3 gFA(Sn / 128, NHn, Bn);         // (16, 16, 2)

    for (int l = 0; l < Lnum; ++l) {
        const float* xf = (l == 0) ? hidden : x2;
        const size_t wb  = (size_t)l * LW_ELEMS;
        const size_t bo1 = (size_t)l * Hn;
        const size_t bio = (size_t)l * FFn;

        bgemm_kernel<4><<<gQKV, 256, GSMEM>>>(xh, xl, wth + wb + LW_QKV, wtl + wb + LW_QKV,
                                              bqkv + (size_t)l*QKVW, nullptr, nullptr,
                                              qkvh, qkvl, Hn, QKVW);

        flashmma_kernel<<<gFA, 256, FSMEM>>>(qkvh, qkvl, mask, cxh, cxl);

        bgemm_kernel<2><<<gAO, 256, GSMEM>>>(cxh, cxl, wth + wb + LW_AO, wtl + wb + LW_AO,
                                             bao + bo1, xf, y, nullptr, nullptr, Hn, Hn);
        ln_kernel<1><<<Mrows, 256>>>(y, g1 + bo1, b1 + bo1, x1, xh, xl);

        bgemm_kernel<5><<<gFF1, 256, GSMEM>>>(xh, xl, wth + wb + LW_I, wtl + wb + LW_I,
                                              bi + bio, nullptr, nullptr, fh, fl, Hn, FFn);
        bgemm_kernel<2><<<gAO, 256, GSMEM>>>(fh, fl, wth + wb + LW_O, wtl + wb + LW_O,
                                             bo + bo1, x1, y, nullptr, nullptr, FFn, Hn);
        if (l == Lnum - 1)
            ln_kernel<0><<<Mrows, 256>>>(y, g2 + bo1, b2 + bo1, outp, nullptr, nullptr);
        else
            ln_kernel<1><<<Mrows, 256>>>(y, g2 + bo1, b2 + bo1, x2, xh, xl);
    }
}